// round 1
// baseline (speedup 1.0000x reference)
#include <cuda_runtime.h>
#include <math.h>

#define SEQ 8192
#define DIM 1024

// Scratch (allocation-free rule: __device__ globals)
__device__ float g_Q[SEQ * DIM];
__device__ float g_K[SEQ * DIM];
__device__ float g_V[SEQ * DIM];
__device__ float g_S[(size_t)SEQ * SEQ];   // 256 MB score/prob matrix (lower-tri blocks used)

// ---------------------------------------------------------------------------
// Tiled fp32 GEMM, 128x128 tile, BK=16, 256 threads, 8x8 per thread.
//   TRANS_B=1: C[M,N] = A[M,K] * B[N,K]^T   (both K-contiguous)  -- QKV, QK^T
//   TRANS_B=0: C[M,N] = A[M,K] * B[K,N]                          -- PV
//   CAUSAL=1 : skip blocks with bx>by, mask j>i to -1e30 on diagonal blocks
//   KVAR=1   : K extent = (by+1)*128 (causal-truncated PV)
// All dims here are multiples of 128/16 -> no bounds checks anywhere.
// ---------------------------------------------------------------------------
template<int TRANS_B, int CAUSAL, int KVAR>
__global__ __launch_bounds__(256, 2)
void gemm128(const float* __restrict__ A, const float* __restrict__ B,
             float* __restrict__ C, int K, int lda, int ldb, int ldc, float scale)
{
    const int BM = 128, BN = 128, BK = 16;
    const int bx = blockIdx.x, by = blockIdx.y;
    if (CAUSAL && bx > by) return;
    if (KVAR) K = (by + 1) * BM;

    __shared__ float As[BK][BM + 4];   // +4 pad: keeps float4 alignment, cuts STS conflicts
    __shared__ float Bs[BK][BN + 4];

    const int tid = threadIdx.x;
    const int tx = tid & 15;           // N micro-tile index
    const int ty = tid >> 4;           // M micro-tile index

    const float* Ab = A + (size_t)by * BM * lda;
    const float* Bb = TRANS_B ? (B + (size_t)bx * BN * ldb) : (B + bx * BN);

    float acc[8][8];
#pragma unroll
    for (int i = 0; i < 8; i++)
#pragma unroll
        for (int j = 0; j < 8; j++) acc[i][j] = 0.f;

    for (int kt = 0; kt < K; kt += BK) {
        // ---- load A tile (transpose K-contiguous rows into As[k][m]) ----
#pragma unroll
        for (int i = 0; i < 2; i++) {
            int f  = i * 256 + tid;            // 512 float4s total
            int r  = f >> 2;                   // 0..127 (M row in tile)
            int c4 = (f & 3) * 4;              // 0,4,8,12 (K offset)
            const float4 v = *(const float4*)(Ab + (size_t)r * lda + kt + c4);
            As[c4 + 0][r] = v.x; As[c4 + 1][r] = v.y;
            As[c4 + 2][r] = v.z; As[c4 + 3][r] = v.w;
        }
        // ---- load B tile ----
        if (TRANS_B) {
#pragma unroll
            for (int i = 0; i < 2; i++) {
                int f  = i * 256 + tid;
                int r  = f >> 2;               // 0..127 (N row in tile)
                int c4 = (f & 3) * 4;
                const float4 v = *(const float4*)(Bb + (size_t)r * ldb + kt + c4);
                Bs[c4 + 0][r] = v.x; Bs[c4 + 1][r] = v.y;
                Bs[c4 + 2][r] = v.z; Bs[c4 + 3][r] = v.w;
            }
        } else {
#pragma unroll
            for (int i = 0; i < 2; i++) {
                int f  = i * 256 + tid;
                int r  = f >> 5;               // 0..15 (K row)
                int cn = (f & 31) * 4;         // 0..124 (N offset)
                const float4 v = *(const float4*)(Bb + (size_t)(kt + r) * ldb + cn);
                *(float4*)&Bs[r][cn] = v;
            }
        }
        __syncthreads();

#pragma unroll
        for (int k = 0; k < BK; k++) {
            float a[8], b[8];
            *(float4*)&a[0] = *(const float4*)&As[k][ty * 8];
            *(float4*)&a[4] = *(const float4*)&As[k][ty * 8 + 4];
            *(float4*)&b[0] = *(const float4*)&Bs[k][tx * 8];
            *(float4*)&b[4] = *(const float4*)&Bs[k][tx * 8 + 4];
#pragma unroll
            for (int i = 0; i < 8; i++)
#pragma unroll
                for (int j = 0; j < 8; j++)
                    acc[i][j] += a[i] * b[j];
        }
        __syncthreads();
    }

    // ---- epilogue ----
    const int row0 = by * BM + ty * 8;
    const int col0 = bx * BN + tx * 8;
#pragma unroll
    for (int i = 0; i < 8; i++) {
        int row = row0 + i;
        float o[8];
#pragma unroll
        for (int j = 0; j < 8; j++) {
            float v = acc[i][j] * scale;
            if (CAUSAL && bx == by && (col0 + j) > row) v = -1e30f;
            o[j] = v;
        }
        *(float4*)(C + (size_t)row * ldc + col0)     = *(float4*)&o[0];
        *(float4*)(C + (size_t)row * ldc + col0 + 4) = *(float4*)&o[4];
    }
}

// ---------------------------------------------------------------------------
// Row softmax over the causal prefix. One CTA per row. The whole row
// (<= 8192 floats = 32KB) is staged in smem: gmem traffic = 1 read + 1 write.
// Masked entries (-1e30 in the diagonal block) become exactly 0.
// ---------------------------------------------------------------------------
__global__ __launch_bounds__(256)
void softmax_rows(float* __restrict__ S)
{
    __shared__ float buf[SEQ];
    __shared__ float red[256];
    const int row = blockIdx.x;
    const int len = ((row >> 7) + 1) << 7;   // block-aligned causal prefix length
    float* Sp = S + (size_t)row * SEQ;
    const int tid = threadIdx.x;

    float lm = -3.4e38f;
    for (int j = tid; j < len; j += 256) {
        float v = Sp[j];
        buf[j] = v;
        lm = fmaxf(lm, v);
    }
    red[tid] = lm; __syncthreads();
    for (int s = 128; s > 0; s >>= 1) {
        if (tid < s) red[tid] = fmaxf(red[tid], red[tid + s]);
        __syncthreads();
    }
    const float m = red[0];
    __syncthreads();

    float ls = 0.f;
    for (int j = tid; j < len; j += 256) {
        float e = __expf(buf[j] - m);
        buf[j] = e;
        ls += e;
    }
    red[tid] = ls; __syncthreads();
    for (int s = 128; s > 0; s >>= 1) {
        if (tid < s) red[tid] += red[tid + s];
        __syncthreads();
    }
    const float inv = 1.f / red[0];

    for (int j = tid; j < len; j += 256)
        Sp[j] = buf[j] * inv;
}

// ---------------------------------------------------------------------------
extern "C" void kernel_launch(void* const* d_in, const int* in_sizes, int n_in,
                              void* d_out, int out_size)
{
    const float* x  = (const float*)d_in[0];
    const float* wq = (const float*)d_in[1];
    const float* wk = (const float*)d_in[2];
    const float* wv = (const float*)d_in[3];
    float* out = (float*)d_out;

    float *Q, *Kp, *V, *S;
    cudaGetSymbolAddress((void**)&Q,  g_Q);
    cudaGetSymbolAddress((void**)&Kp, g_K);
    cudaGetSymbolAddress((void**)&V,  g_V);
    cudaGetSymbolAddress((void**)&S,  g_S);

    dim3 thr(256);
    dim3 gproj(DIM / 128, SEQ / 128);   // (8, 64)
    dim3 gsc(SEQ / 128, SEQ / 128);     // (64, 64)

    // QKV projections: y = x @ W^T
    gemm128<1, 0, 0><<<gproj, thr>>>(x, wq, Q,  DIM, DIM, DIM, DIM, 1.f);
    gemm128<1, 0, 0><<<gproj, thr>>>(x, wk, Kp, DIM, DIM, DIM, DIM, 1.f);
    gemm128<1, 0, 0><<<gproj, thr>>>(x, wv, V,  DIM, DIM, DIM, DIM, 1.f);

    // Scores: S = (Q @ K^T) / 32, causal (lower-tri blocks only, diag masked)
    gemm128<1, 1, 0><<<gsc, thr>>>(Q, Kp, S, DIM, DIM, DIM, SEQ, 0.03125f);

    // Row softmax over causal prefix
    softmax_rows<<<SEQ, thr>>>(S);

    // Output: O = P @ V, K extent truncated per row-block
    gemm128<0, 0, 1><<<gproj, thr>>>(S, V, out, 0, SEQ, DIM, DIM, 1.f);
}

// round 2
// speedup vs baseline: 2.1608x; 2.1608x over previous
#include <cuda_runtime.h>
#include <math.h>
#include <stdint.h>

#define SEQ 8192
#define DIM 1024

// Scratch (allocation-free rule: __device__ globals)
__device__ float g_Q[SEQ * DIM];
__device__ float g_K[SEQ * DIM];
__device__ float g_V[SEQ * DIM];
__device__ float g_S[(size_t)SEQ * SEQ];   // 256 MB scores/probs (lower-tri blocks used)

__device__ __forceinline__ uint32_t f2tf32(float x) {
    uint32_t r;
    asm("cvt.rna.tf32.f32 %0, %1;" : "=r"(r) : "f"(x));
    return r;
}

__device__ __forceinline__ void mma_tf32(float* c, const uint32_t* a, const uint32_t* b) {
    asm volatile(
        "mma.sync.aligned.m16n8k8.row.col.f32.tf32.tf32.f32 "
        "{%0,%1,%2,%3}, {%4,%5,%6,%7}, {%8,%9}, {%0,%1,%2,%3};\n"
        : "+f"(c[0]), "+f"(c[1]), "+f"(c[2]), "+f"(c[3])
        : "r"(a[0]), "r"(a[1]), "r"(a[2]), "r"(a[3]), "r"(b[0]), "r"(b[1]));
}

// ---------------------------------------------------------------------------
// TF32 tensor-core GEMM, 128x128 tile, BK=32, 256 threads (8 warps, 2x4).
// Warp tile 64x32 via m16n8k8: 4 m-frags x 4 n-frags.
//   TRANS_B=1: C[M,N] = A[M,K] * B[N,K]^T   (both K-contiguous)  -- QKV, QK^T
//   TRANS_B=0: C[M,N] = A[M,K] * B[K,N]                          -- PV
//   CAUSAL=1 : skip blocks bx>by, mask j>i to -1e30 on diagonal blocks
//   KVAR=1   : K extent = (by+1)*128 (causal-truncated PV)
// smem stride 36 (= 4 mod 32) makes all fragment LDS conflict-free.
// ---------------------------------------------------------------------------
template<int TRANS_B, int CAUSAL, int KVAR>
__global__ __launch_bounds__(256, 2)
void gemm_tc(const float* __restrict__ A, const float* __restrict__ B,
             float* __restrict__ C, int K, int lda, int ldb, int ldc, float scale)
{
    const int BM = 128, BN = 128, BK = 32;
    const int bx = blockIdx.x, by = blockIdx.y;
    if (CAUSAL && bx > by) return;
    if (KVAR) K = (by + 1) * BM;

    __shared__ uint32_t As[BM][BK + 4];   // [m][k], tf32 bits
    __shared__ uint32_t Bs[BN][BK + 4];   // [n][k], tf32 bits

    const int tid  = threadIdx.x;
    const int wid  = tid >> 5;
    const int lane = tid & 31;
    const int l4 = lane >> 2;        // 0..7
    const int lq = lane & 3;         // 0..3
    const int wm = (wid >> 2) * 64;  // warp m offset (0/64)
    const int wn = (wid & 3) * 32;   // warp n offset (0/32/64/96)

    const float* Ab = A + (size_t)by * BM * lda;
    const float* Bb = TRANS_B ? (B + (size_t)bx * BN * ldb) : (B + bx * BN);

    float acc[4][4][4];
#pragma unroll
    for (int i = 0; i < 4; i++)
#pragma unroll
        for (int j = 0; j < 4; j++)
#pragma unroll
            for (int e = 0; e < 4; e++) acc[i][j][e] = 0.f;

    for (int kt = 0; kt < K; kt += BK) {
        // ---- stage A tile: rows K-contiguous, convert to tf32 ----
#pragma unroll
        for (int i = 0; i < 4; i++) {
            int f = i * 256 + tid;           // 1024 float4s
            int r = f >> 3;                  // 0..127
            int c = (f & 7) * 4;             // 0..28
            const float4 v = *(const float4*)(Ab + (size_t)r * lda + kt + c);
            uint32_t* s = &As[r][c];
            s[0] = f2tf32(v.x); s[1] = f2tf32(v.y);
            s[2] = f2tf32(v.z); s[3] = f2tf32(v.w);
        }
        // ---- stage B tile ----
        if (TRANS_B) {
#pragma unroll
            for (int i = 0; i < 4; i++) {
                int f = i * 256 + tid;
                int r = f >> 3;
                int c = (f & 7) * 4;
                const float4 v = *(const float4*)(Bb + (size_t)r * ldb + kt + c);
                uint32_t* s = &Bs[r][c];
                s[0] = f2tf32(v.x); s[1] = f2tf32(v.y);
                s[2] = f2tf32(v.z); s[3] = f2tf32(v.w);
            }
        } else {
            // global B is [K][N]; transpose into Bs[n][k]
#pragma unroll
            for (int i = 0; i < 4; i++) {
                int f  = i * 256 + tid;
                int kr = f >> 5;             // 0..31
                int nc = (f & 31) * 4;       // 0..124
                const float4 v = *(const float4*)(Bb + (size_t)(kt + kr) * ldb + nc);
                Bs[nc + 0][kr] = f2tf32(v.x);
                Bs[nc + 1][kr] = f2tf32(v.y);
                Bs[nc + 2][kr] = f2tf32(v.z);
                Bs[nc + 3][kr] = f2tf32(v.w);
            }
        }
        __syncthreads();

        // ---- 4 k-steps of 8 ----
#pragma unroll
        for (int ks = 0; ks < 4; ks++) {
            const int k0 = ks * 8;
            uint32_t a[4][4], b[4][2];
#pragma unroll
            for (int mi = 0; mi < 4; mi++) {
                int r0 = wm + mi * 16 + l4;
                a[mi][0] = As[r0][k0 + lq];
                a[mi][1] = As[r0 + 8][k0 + lq];
                a[mi][2] = As[r0][k0 + lq + 4];
                a[mi][3] = As[r0 + 8][k0 + lq + 4];
            }
#pragma unroll
            for (int ni = 0; ni < 4; ni++) {
                int rn = wn + ni * 8 + l4;
                b[ni][0] = Bs[rn][k0 + lq];
                b[ni][1] = Bs[rn][k0 + lq + 4];
            }
#pragma unroll
            for (int mi = 0; mi < 4; mi++)
#pragma unroll
                for (int ni = 0; ni < 4; ni++)
                    mma_tf32(acc[mi][ni], a[mi], b[ni]);
        }
        __syncthreads();
    }

    // ---- epilogue ----
#pragma unroll
    for (int mi = 0; mi < 4; mi++) {
        const int gr0 = by * BM + wm + mi * 16 + l4;
        const int gr1 = gr0 + 8;
#pragma unroll
        for (int ni = 0; ni < 4; ni++) {
            const int gc = bx * BN + wn + ni * 8 + 2 * lq;
            float v0 = acc[mi][ni][0] * scale;
            float v1 = acc[mi][ni][1] * scale;
            float v2 = acc[mi][ni][2] * scale;
            float v3 = acc[mi][ni][3] * scale;
            if (CAUSAL && bx == by) {
                if (gc     > gr0) v0 = -1e30f;
                if (gc + 1 > gr0) v1 = -1e30f;
                if (gc     > gr1) v2 = -1e30f;
                if (gc + 1 > gr1) v3 = -1e30f;
            }
            *(float2*)(C + (size_t)gr0 * ldc + gc) = make_float2(v0, v1);
            *(float2*)(C + (size_t)gr1 * ldc + gc) = make_float2(v2, v3);
        }
    }
}

// ---------------------------------------------------------------------------
// Row softmax over the causal prefix. One CTA per row; row staged in smem.
// ---------------------------------------------------------------------------
__global__ __launch_bounds__(256)
void softmax_rows(float* __restrict__ S)
{
    __shared__ float buf[SEQ];
    __shared__ float red[256];
    const int row = blockIdx.x;
    const int len = ((row >> 7) + 1) << 7;   // block-aligned causal prefix length
    float* Sp = S + (size_t)row * SEQ;
    const int tid = threadIdx.x;

    float lm = -3.4e38f;
    for (int j = tid; j < len; j += 256) {
        float v = Sp[j];
        buf[j] = v;
        lm = fmaxf(lm, v);
    }
    red[tid] = lm; __syncthreads();
    for (int s = 128; s > 0; s >>= 1) {
        if (tid < s) red[tid] = fmaxf(red[tid], red[tid + s]);
        __syncthreads();
    }
    const float m = red[0];
    __syncthreads();

    float ls = 0.f;
    for (int j = tid; j < len; j += 256) {
        float e = __expf(buf[j] - m);
        buf[j] = e;
        ls += e;
    }
    red[tid] = ls; __syncthreads();
    for (int s = 128; s > 0; s >>= 1) {
        if (tid < s) red[tid] += red[tid + s];
        __syncthreads();
    }
    const float inv = 1.f / red[0];

    for (int j = tid; j < len; j += 256)
        Sp[j] = buf[j] * inv;
}

// ---------------------------------------------------------------------------
extern "C" void kernel_launch(void* const* d_in, const int* in_sizes, int n_in,
                              void* d_out, int out_size)
{
    const float* x  = (const float*)d_in[0];
    const float* wq = (const float*)d_in[1];
    const float* wk = (const float*)d_in[2];
    const float* wv = (const float*)d_in[3];
    float* out = (float*)d_out;

    float *Q, *Kp, *V, *S;
    cudaGetSymbolAddress((void**)&Q,  g_Q);
    cudaGetSymbolAddress((void**)&Kp, g_K);
    cudaGetSymbolAddress((void**)&V,  g_V);
    cudaGetSymbolAddress((void**)&S,  g_S);

    dim3 thr(256);
    dim3 gproj(DIM / 128, SEQ / 128);   // (8, 64)
    dim3 gsc(SEQ / 128, SEQ / 128);     // (64, 64)

    // QKV projections: y = x @ W^T
    gemm_tc<1, 0, 0><<<gproj, thr>>>(x, wq, Q,  DIM, DIM, DIM, DIM, 1.f);
    gemm_tc<1, 0, 0><<<gproj, thr>>>(x, wk, Kp, DIM, DIM, DIM, DIM, 1.f);
    gemm_tc<1, 0, 0><<<gproj, thr>>>(x, wv, V,  DIM, DIM, DIM, DIM, 1.f);

    // Scores: S = (Q @ K^T) / 32, causal (lower-tri blocks only, diag masked)
    gemm_tc<1, 1, 0><<<gsc, thr>>>(Q, Kp, S, DIM, DIM, DIM, SEQ, 0.03125f);

    // Row softmax over causal prefix
    softmax_rows<<<SEQ, thr>>>(S);

    // Output: O = P @ V, K extent truncated per row-block
    gemm_tc<0, 0, 1><<<gproj, thr>>>(S, V, out, 0, SEQ, DIM, DIM, 1.f);
}

// round 4
// speedup vs baseline: 3.2674x; 1.5121x over previous
#include <cuda_runtime.h>
#include <math.h>
#include <stdint.h>

#define SEQ 8192
#define DIM 1024

// ---- scratch (__device__ globals; no allocs allowed) ----
__device__ float g_Q [SEQ * DIM];
__device__ float g_K [SEQ * DIM];
__device__ float g_V [SEQ * DIM];
__device__ float g_Vt[DIM * SEQ];          // V^T, tf32-rounded (K-major B for PV)
__device__ float g_X [SEQ * DIM];          // x,  tf32-rounded
__device__ float g_Wq[DIM * DIM];
__device__ float g_Wk[DIM * DIM];
__device__ float g_Wv[DIM * DIM];
__device__ float g_S [(size_t)SEQ * SEQ];  // 256MB scores/probs

// ---------------------------------------------------------------------------
__device__ __forceinline__ uint32_t smem_u32(const void* p) {
    uint32_t a;
    asm("{ .reg .u64 t; cvta.to.shared.u64 t, %1; cvt.u32.u64 %0, t; }" : "=r"(a) : "l"(p));
    return a;
}
__device__ __forceinline__ float tf32r(float x) {
    uint32_t r;
    asm("cvt.rna.tf32.f32 %0, %1;" : "=r"(r) : "f"(x));
    return __uint_as_float(r);
}
__device__ __forceinline__ void mma_tf32(float* c, const uint32_t* a, const uint32_t* b) {
    asm volatile(
        "mma.sync.aligned.m16n8k8.row.col.f32.tf32.tf32.f32 "
        "{%0,%1,%2,%3}, {%4,%5,%6,%7}, {%8,%9}, {%0,%1,%2,%3};\n"
        : "+f"(c[0]), "+f"(c[1]), "+f"(c[2]), "+f"(c[3])
        : "r"(a[0]), "r"(a[1]), "r"(a[2]), "r"(a[3]), "r"(b[0]), "r"(b[1]));
}
#define CP16(dst, src) \
    asm volatile("cp.async.cg.shared.global [%0], [%1], 16;" :: "r"(dst), "l"(src) : "memory")

// ---------------------------------------------------------------------------
// TF32 tensor GEMM: C = A[M,K] * B[N,K]^T (both K-major, values pre-rounded
// to tf32). 128x128 tile, BK=32, 2-stage cp.async double buffer, 8 warps,
// warp tile 64x32 (m16n8k8, 4x4 frags). smem row stride 36 -> conflict-free.
//   CAUSAL=1: skip bx>by, mask col>row on diagonal tiles
//   KVAR=1  : K = (by+1)*128 (causal-truncated PV)
//   ROUND=1 : tf32-round output (feeds a later MMA)
// ---------------------------------------------------------------------------
template<int CAUSAL, int KVAR, int ROUND>
__global__ void __launch_bounds__(256, 2)
gemm_tc(const float* __restrict__ A, const float* __restrict__ B, float* __restrict__ C,
        int K, int lda, int ldb, int ldc, float scale)
{
    const int bx = blockIdx.x, by = blockIdx.y;
    if (CAUSAL && bx > by) return;
    if (KVAR) K = (by + 1) * 128;
    const int NT = K >> 5;                       // number of 32-wide K tiles

    extern __shared__ float smem[];              // 2 stages * (A+B) * 128*36
    const uint32_t sbase = smem_u32(smem);
    const int STAGE_B = 2 * 128 * 36 * 4;        // 36864 bytes per stage

    const int tid  = threadIdx.x;
    const int wid  = tid >> 5;
    const int lane = tid & 31;
    const int l4 = lane >> 2, lq = lane & 3;
    const int wm = (wid >> 2) * 64;              // warp m offset
    const int wn = (wid & 3) * 32;               // warp n offset

    const float* Ag = A + (size_t)by * 128 * lda;
    const float* Bg = B + (size_t)bx * 128 * ldb;

    float acc[4][4][4];
#pragma unroll
    for (int i = 0; i < 4; i++)
#pragma unroll
        for (int j = 0; j < 4; j++)
#pragma unroll
            for (int e = 0; e < 4; e++) acc[i][j][e] = 0.f;

    // stage filler: 128 rows x 32 floats for A and B, 16B per cp.async
#define PRODUCE(t) do {                                                       \
        const float* _Ab = Ag + (t) * 32;                                     \
        const float* _Bb = Bg + (t) * 32;                                     \
        const uint32_t _sA = sbase + ((t) & 1) * STAGE_B;                     \
        const uint32_t _sB = _sA + 128 * 36 * 4;                              \
        _Pragma("unroll")                                                     \
        for (int _j = 0; _j < 4; _j++) {                                      \
            int _q = _j * 256 + tid;                                          \
            int _r = _q >> 3, _c = _q & 7;                                    \
            uint32_t _so = _r * 144 + _c * 16;                                \
            CP16(_sA + _so, _Ab + (size_t)_r * lda + _c * 4);                 \
            CP16(_sB + _so, _Bb + (size_t)_r * ldb + _c * 4);                 \
        }                                                                     \
        asm volatile("cp.async.commit_group;" ::: "memory");                  \
    } while (0)

    PRODUCE(0);
    for (int i = 0; i < NT; i++) {
        if (i + 1 < NT) {
            PRODUCE(i + 1);
            asm volatile("cp.async.wait_group 1;" ::: "memory");
        } else {
            asm volatile("cp.async.wait_group 0;" ::: "memory");
        }
        __syncthreads();

        const uint32_t* As = (const uint32_t*)smem + (i & 1) * (STAGE_B / 4);
        const uint32_t* Bs = As + 128 * 36;

#pragma unroll
        for (int ks = 0; ks < 4; ks++) {
            const int k0 = ks * 8;
            uint32_t a[4][4], b[4][2];
#pragma unroll
            for (int mi = 0; mi < 4; mi++) {
                int r0 = (wm + mi * 16 + l4) * 36;
                a[mi][0] = As[r0       + k0 + lq];
                a[mi][1] = As[r0 + 288 + k0 + lq];        // +8 rows
                a[mi][2] = As[r0       + k0 + lq + 4];
                a[mi][3] = As[r0 + 288 + k0 + lq + 4];
            }
#pragma unroll
            for (int ni = 0; ni < 4; ni++) {
                int rn = (wn + ni * 8 + l4) * 36;
                b[ni][0] = Bs[rn + k0 + lq];
                b[ni][1] = Bs[rn + k0 + lq + 4];
            }
#pragma unroll
            for (int mi = 0; mi < 4; mi++)
#pragma unroll
                for (int ni = 0; ni < 4; ni++)
                    mma_tf32(acc[mi][ni], a[mi], b[ni]);
        }
        __syncthreads();
    }
#undef PRODUCE

    // ---- epilogue ----
#pragma unroll
    for (int mi = 0; mi < 4; mi++) {
        const int gr0 = by * 128 + wm + mi * 16 + l4;
        const int gr1 = gr0 + 8;
#pragma unroll
        for (int ni = 0; ni < 4; ni++) {
            const int gc = bx * 128 + wn + ni * 8 + 2 * lq;
            float v0 = acc[mi][ni][0] * scale;
            float v1 = acc[mi][ni][1] * scale;
            float v2 = acc[mi][ni][2] * scale;
            float v3 = acc[mi][ni][3] * scale;
            if (CAUSAL && bx == by) {
                if (gc     > gr0) v0 = -1e30f;
                if (gc + 1 > gr0) v1 = -1e30f;
                if (gc     > gr1) v2 = -1e30f;
                if (gc + 1 > gr1) v3 = -1e30f;
            }
            if (ROUND) { v0 = tf32r(v0); v1 = tf32r(v1); v2 = tf32r(v2); v3 = tf32r(v3); }
            *(float2*)(C + (size_t)gr0 * ldc + gc) = make_float2(v0, v1);
            *(float2*)(C + (size_t)gr1 * ldc + gc) = make_float2(v2, v3);
        }
    }
}

// ---------------------------------------------------------------------------
__global__ void __launch_bounds__(256) round_tf32_k(const float* __restrict__ s,
                                                    float* __restrict__ d, int n)
{
    int i = (blockIdx.x * 256 + threadIdx.x) * 4;
    if (i < n) {
        float4 v = *(const float4*)(s + i);
        v.x = tf32r(v.x); v.y = tf32r(v.y); v.z = tf32r(v.z); v.w = tf32r(v.w);
        *(float4*)(d + i) = v;
    }
}

// V[SEQ][DIM] -> Vt[DIM][SEQ], tf32-rounded
__global__ void __launch_bounds__(256) transpose_rnd(const float* __restrict__ src,
                                                     float* __restrict__ dst)
{
    __shared__ float t[32][33];
    const int x = blockIdx.x * 32 + threadIdx.x;
    const int y0 = blockIdx.y * 32;
    for (int j = threadIdx.y; j < 32; j += 8)
        t[j][threadIdx.x] = src[(size_t)(y0 + j) * DIM + x];
    __syncthreads();
    const int xo = y0 + threadIdx.x;
    const int yo0 = blockIdx.x * 32;
    for (int j = threadIdx.y; j < 32; j += 8)
        dst[(size_t)(yo0 + j) * SEQ + xo] = tf32r(t[threadIdx.x][j]);
}

// row softmax over causal prefix; writes tf32-rounded probs
__global__ void __launch_bounds__(256) softmax_rows(float* __restrict__ S)
{
    __shared__ float buf[SEQ];
    __shared__ float red[256];
    const int row = blockIdx.x;
    const int len = ((row >> 7) + 1) << 7;
    float* Sp = S + (size_t)row * SEQ;
    const int tid = threadIdx.x;

    float lm = -3.4e38f;
    for (int j = tid; j < len; j += 256) { float v = Sp[j]; buf[j] = v; lm = fmaxf(lm, v); }
    red[tid] = lm; __syncthreads();
    for (int s = 128; s > 0; s >>= 1) { if (tid < s) red[tid] = fmaxf(red[tid], red[tid + s]); __syncthreads(); }
    const float m = red[0]; __syncthreads();

    float ls = 0.f;
    for (int j = tid; j < len; j += 256) { float e = __expf(buf[j] - m); buf[j] = e; ls += e; }
    red[tid] = ls; __syncthreads();
    for (int s = 128; s > 0; s >>= 1) { if (tid < s) red[tid] += red[tid + s]; __syncthreads(); }
    const float inv = 1.f / red[0];

    for (int j = tid; j < len; j += 256) Sp[j] = tf32r(buf[j] * inv);
}

// ---------------------------------------------------------------------------
extern "C" void kernel_launch(void* const* d_in, const int* in_sizes, int n_in,
                              void* d_out, int out_size)
{
    const float* x  = (const float*)d_in[0];
    const float* wq = (const float*)d_in[1];
    const float* wk = (const float*)d_in[2];
    const float* wv = (const float*)d_in[3];
    float* out = (float*)d_out;

    float *Q, *Kp, *V, *Vt, *X, *Wq, *Wk, *Wv, *S;
    cudaGetSymbolAddress((void**)&Q,  g_Q);
    cudaGetSymbolAddress((void**)&Kp, g_K);
    cudaGetSymbolAddress((void**)&V,  g_V);
    cudaGetSymbolAddress((void**)&Vt, g_Vt);
    cudaGetSymbolAddress((void**)&X,  g_X);
    cudaGetSymbolAddress((void**)&Wq, g_Wq);
    cudaGetSymbolAddress((void**)&Wk, g_Wk);
    cudaGetSymbolAddress((void**)&Wv, g_Wv);
    cudaGetSymbolAddress((void**)&S,  g_S);

    const int SMEM_DYN = 2 * 2 * 128 * 36 * 4;   // 73728 bytes
    cudaFuncSetAttribute(gemm_tc<0,0,1>, cudaFuncAttributeMaxDynamicSharedMemorySize, SMEM_DYN);
    cudaFuncSetAttribute(gemm_tc<0,0,0>, cudaFuncAttributeMaxDynamicSharedMemorySize, SMEM_DYN);
    cudaFuncSetAttribute(gemm_tc<1,0,0>, cudaFuncAttributeMaxDynamicSharedMemorySize, SMEM_DYN);
    cudaFuncSetAttribute(gemm_tc<0,1,0>, cudaFuncAttributeMaxDynamicSharedMemorySize, SMEM_DYN);

    // tf32-round all first-GEMM operands (hoists cvt out of GEMM hot loops)
    round_tf32_k<<<SEQ * DIM / 1024, 256>>>(x,  X,  SEQ * DIM);
    round_tf32_k<<<DIM * DIM / 1024, 256>>>(wq, Wq, DIM * DIM);
    round_tf32_k<<<DIM * DIM / 1024, 256>>>(wk, Wk, DIM * DIM);
    round_tf32_k<<<DIM * DIM / 1024, 256>>>(wv, Wv, DIM * DIM);

    dim3 thr(256);
    dim3 gproj(DIM / 128, SEQ / 128);   // (8, 64)
    dim3 gsc(SEQ / 128, SEQ / 128);     // (64, 64)

    // QKV projections (Q,K rounded in epilogue; V rounded in transpose)
    gemm_tc<0,0,1><<<gproj, thr, SMEM_DYN>>>(X, Wq, Q,  DIM, DIM, DIM, DIM, 1.f);
    gemm_tc<0,0,1><<<gproj, thr, SMEM_DYN>>>(X, Wk, Kp, DIM, DIM, DIM, DIM, 1.f);
    gemm_tc<0,0,0><<<gproj, thr, SMEM_DYN>>>(X, Wv, V,  DIM, DIM, DIM, DIM, 1.f);

    transpose_rnd<<<dim3(DIM / 32, SEQ / 32), dim3(32, 8)>>>(V, Vt);

    // scores (lower-tri blocks only, diagonal masked)
    gemm_tc<1,0,0><<<gsc, thr, SMEM_DYN>>>(Q, Kp, S, DIM, DIM, DIM, SEQ, 0.03125f);

    softmax_rows<<<SEQ, thr>>>(S);

    // out = P @ V = P * Vt^T (both K-major), causal-truncated K per row block
    gemm_tc<0,1,0><<<gproj, thr, SMEM_DYN>>>(S, Vt, out, 0, SEQ, SEQ, DIM, 1.f);
}

// round 6
// speedup vs baseline: 3.4322x; 1.0504x over previous
#include <cuda_runtime.h>
#include <math.h>
#include <stdint.h>

#define SEQ 8192
#define DIM 1024

// ---- scratch (__device__ globals; no allocs allowed) ----
__device__ float g_Q [SEQ * DIM];
__device__ float g_K [SEQ * DIM];
__device__ float g_V [SEQ * DIM];
__device__ float g_Vt[DIM * SEQ];          // V^T, tf32-rounded (K-major B for PV)
__device__ float g_X [SEQ * DIM];          // x,  tf32-rounded
__device__ float g_Wq[DIM * DIM];
__device__ float g_Wk[DIM * DIM];
__device__ float g_Wv[DIM * DIM];
__device__ float g_S [(size_t)SEQ * SEQ];  // 256MB scores/probs

// ---------------------------------------------------------------------------
__device__ __forceinline__ uint32_t smem_u32(const void* p) {
    uint32_t a;
    asm("{ .reg .u64 t; cvta.to.shared.u64 t, %1; cvt.u32.u64 %0, t; }" : "=r"(a) : "l"(p));
    return a;
}
__device__ __forceinline__ float tf32r(float x) {
    uint32_t r;
    asm("cvt.rna.tf32.f32 %0, %1;" : "=r"(r) : "f"(x));
    return __uint_as_float(r);
}
__device__ __forceinline__ void mma_tf32(float* c, const uint32_t* a, const uint32_t* b) {
    asm volatile(
        "mma.sync.aligned.m16n8k8.row.col.f32.tf32.tf32.f32 "
        "{%0,%1,%2,%3}, {%4,%5,%6,%7}, {%8,%9}, {%0,%1,%2,%3};\n"
        : "+f"(c[0]), "+f"(c[1]), "+f"(c[2]), "+f"(c[3])
        : "r"(a[0]), "r"(a[1]), "r"(a[2]), "r"(a[3]), "r"(b[0]), "r"(b[1]));
}
#define CP16(dst, src) \
    asm volatile("cp.async.cg.shared.global [%0], [%1], 16;" :: "r"(dst), "l"(src) : "memory")

// ---------------------------------------------------------------------------
// TF32 tensor GEMM: C = A[M,K] * B[N,K]^T (both K-major, values pre-rounded
// to tf32). 128x128 CTA tile, BK=32, 2-stage cp.async double buffer.
// 4 warps (128 thr), warp tile 64x64 (m16n8k8, 4x8 frags) -> 1.0 LDS/HMMA.
// smem row stride 36 words -> conflict-free fragment loads.
//   CAUSAL=1: skip bx>by, mask col>row on diagonal tiles
//   KVAR=1  : K = (by+1)*128 (causal-truncated PV)
//   ROUND=1 : tf32-round output (feeds a later MMA)
// ---------------------------------------------------------------------------
template<int CAUSAL, int KVAR, int ROUND>
__global__ void __launch_bounds__(128, 2)
gemm_tc(const float* __restrict__ A, const float* __restrict__ B, float* __restrict__ C,
        int K, int lda, int ldb, int ldc, float scale)
{
    const int bx = blockIdx.x, by = blockIdx.y;
    if (CAUSAL && bx > by) return;
    if (KVAR) K = (by + 1) * 128;
    const int NT = K >> 5;                       // number of 32-wide K tiles

    extern __shared__ float smem[];              // 2 stages * (A+B) * 128*36
    const uint32_t sbase = smem_u32(smem);
    const int STAGE_B = 2 * 128 * 36 * 4;        // 36864 bytes per stage

    const int tid  = threadIdx.x;
    const int wid  = tid >> 5;
    const int lane = tid & 31;
    const int l4 = lane >> 2, lq = lane & 3;
    const int wm = (wid >> 1) * 64;              // warp m offset (0/64)
    const int wn = (wid & 1) * 64;               // warp n offset (0/64)

    const float* Ag = A + (size_t)by * 128 * lda;
    const float* Bg = B + (size_t)bx * 128 * ldb;

    float acc[4][8][4];
#pragma unroll
    for (int i = 0; i < 4; i++)
#pragma unroll
        for (int j = 0; j < 8; j++)
#pragma unroll
            for (int e = 0; e < 4; e++) acc[i][j][e] = 0.f;

    // stage filler: 128 rows x 32 floats (8x16B granules) for A and B
#define PRODUCE(t) do {                                                       \
        const float* _Ab = Ag + (t) * 32;                                     \
        const float* _Bb = Bg + (t) * 32;                                     \
        const uint32_t _sA = sbase + ((t) & 1) * STAGE_B;                     \
        const uint32_t _sB = _sA + 128 * 36 * 4;                              \
        _Pragma("unroll")                                                     \
        for (int _j = 0; _j < 8; _j++) {                                      \
            int _q = _j * 128 + tid;                                          \
            int _r = _q >> 3, _c = _q & 7;                                    \
            uint32_t _so = _r * 144 + _c * 16;                                \
            CP16(_sA + _so, _Ab + (size_t)_r * lda + _c * 4);                 \
            CP16(_sB + _so, _Bb + (size_t)_r * ldb + _c * 4);                 \
        }                                                                     \
        asm volatile("cp.async.commit_group;" ::: "memory");                  \
    } while (0)

    PRODUCE(0);
    for (int i = 0; i < NT; i++) {
        if (i + 1 < NT) {
            PRODUCE(i + 1);
            asm volatile("cp.async.wait_group 1;" ::: "memory");
        } else {
            asm volatile("cp.async.wait_group 0;" ::: "memory");
        }
        __syncthreads();

        const uint32_t* As = (const uint32_t*)smem + (i & 1) * (STAGE_B / 4);
        const uint32_t* Bs = As + 128 * 36;

#pragma unroll
        for (int ks = 0; ks < 4; ks++) {
            const int k0 = ks * 8;
            uint32_t a[4][4], b[8][2];
#pragma unroll
            for (int mi = 0; mi < 4; mi++) {
                int r0 = (wm + mi * 16 + l4) * 36;
                a[mi][0] = As[r0       + k0 + lq];
                a[mi][1] = As[r0 + 288 + k0 + lq];        // +8 rows
                a[mi][2] = As[r0       + k0 + lq + 4];
                a[mi][3] = As[r0 + 288 + k0 + lq + 4];
            }
#pragma unroll
            for (int ni = 0; ni < 8; ni++) {
                int rn = (wn + ni * 8 + l4) * 36;
                b[ni][0] = Bs[rn + k0 + lq];
                b[ni][1] = Bs[rn + k0 + lq + 4];
            }
#pragma unroll
            for (int mi = 0; mi < 4; mi++)
#pragma unroll
                for (int ni = 0; ni < 8; ni++)
                    mma_tf32(acc[mi][ni], a[mi], b[ni]);
        }
        __syncthreads();
    }
#undef PRODUCE

    // ---- epilogue ----
#pragma unroll
    for (int mi = 0; mi < 4; mi++) {
        const int gr0 = by * 128 + wm + mi * 16 + l4;
        const int gr1 = gr0 + 8;
#pragma unroll
        for (int ni = 0; ni < 8; ni++) {
            const int gc = bx * 128 + wn + ni * 8 + 2 * lq;
            float v0 = acc[mi][ni][0] * scale;
            float v1 = acc[mi][ni][1] * scale;
            float v2 = acc[mi][ni][2] * scale;
            float v3 = acc[mi][ni][3] * scale;
            if (CAUSAL && bx == by) {
                if (gc     > gr0) v0 = -1e30f;
                if (gc + 1 > gr0) v1 = -1e30f;
                if (gc     > gr1) v2 = -1e30f;
                if (gc + 1 > gr1) v3 = -1e30f;
            }
            if (ROUND) { v0 = tf32r(v0); v1 = tf32r(v1); v2 = tf32r(v2); v3 = tf32r(v3); }
            *(float2*)(C + (size_t)gr0 * ldc + gc) = make_float2(v0, v1);
            *(float2*)(C + (size_t)gr1 * ldc + gc) = make_float2(v2, v3);
        }
    }
}

// ---------------------------------------------------------------------------
__global__ void __launch_bounds__(256) round_tf32_k(const float* __restrict__ s,
                                                    float* __restrict__ d, int n)
{
    int i = (blockIdx.x * 256 + threadIdx.x) * 4;
    if (i < n) {
        float4 v = *(const float4*)(s + i);
        v.x = tf32r(v.x); v.y = tf32r(v.y); v.z = tf32r(v.z); v.w = tf32r(v.w);
        *(float4*)(d + i) = v;
    }
}

// V[SEQ][DIM] -> Vt[DIM][SEQ], tf32-rounded
__global__ void __launch_bounds__(256) transpose_rnd(const float* __restrict__ src,
                                                     float* __restrict__ dst)
{
    __shared__ float t[32][33];
    const int x = blockIdx.x * 32 + threadIdx.x;
    const int y0 = blockIdx.y * 32;
    for (int j = threadIdx.y; j < 32; j += 8)
        t[j][threadIdx.x] = src[(size_t)(y0 + j) * DIM + x];
    __syncthreads();
    const int xo = y0 + threadIdx.x;
    const int yo0 = blockIdx.x * 32;
    for (int j = threadIdx.y; j < 32; j += 8)
        dst[(size_t)(yo0 + j) * SEQ + xo] = tf32r(t[threadIdx.x][j]);
}

// row softmax over causal prefix; REQUIRES blockDim.x == 256
__global__ void __launch_bounds__(256) softmax_rows(float* __restrict__ S)
{
    __shared__ float buf[SEQ];
    __shared__ float red[256];
    const int row = blockIdx.x;
    const int len = ((row >> 7) + 1) << 7;
    float* Sp = S + (size_t)row * SEQ;
    const int tid = threadIdx.x;

    float lm = -3.4e38f;
    for (int j = tid; j < len; j += 256) { float v = Sp[j]; buf[j] = v; lm = fmaxf(lm, v); }
    red[tid] = lm; __syncthreads();
    for (int s = 128; s > 0; s >>= 1) { if (tid < s) red[tid] = fmaxf(red[tid], red[tid + s]); __syncthreads(); }
    const float m = red[0]; __syncthreads();

    float ls = 0.f;
    for (int j = tid; j < len; j += 256) { float e = __expf(buf[j] - m); buf[j] = e; ls += e; }
    red[tid] = ls; __syncthreads();
    for (int s = 128; s > 0; s >>= 1) { if (tid < s) red[tid] += red[tid + s]; __syncthreads(); }
    const float inv = 1.f / red[0];

    for (int j = tid; j < len; j += 256) Sp[j] = tf32r(buf[j] * inv);
}

// ---------------------------------------------------------------------------
extern "C" void kernel_launch(void* const* d_in, const int* in_sizes, int n_in,
                              void* d_out, int out_size)
{
    const float* x  = (const float*)d_in[0];
    const float* wq = (const float*)d_in[1];
    const float* wk = (const float*)d_in[2];
    const float* wv = (const float*)d_in[3];
    float* out = (float*)d_out;

    float *Q, *Kp, *V, *Vt, *X, *Wq, *Wk, *Wv, *S;
    cudaGetSymbolAddress((void**)&Q,  g_Q);
    cudaGetSymbolAddress((void**)&Kp, g_K);
    cudaGetSymbolAddress((void**)&V,  g_V);
    cudaGetSymbolAddress((void**)&Vt, g_Vt);
    cudaGetSymbolAddress((void**)&X,  g_X);
    cudaGetSymbolAddress((void**)&Wq, g_Wq);
    cudaGetSymbolAddress((void**)&Wk, g_Wk);
    cudaGetSymbolAddress((void**)&Wv, g_Wv);
    cudaGetSymbolAddress((void**)&S,  g_S);

    const int SMEM_DYN = 2 * 2 * 128 * 36 * 4;   // 73728 bytes
    cudaFuncSetAttribute(gemm_tc<0,0,1>, cudaFuncAttributeMaxDynamicSharedMemorySize, SMEM_DYN);
    cudaFuncSetAttribute(gemm_tc<0,0,0>, cudaFuncAttributeMaxDynamicSharedMemorySize, SMEM_DYN);
    cudaFuncSetAttribute(gemm_tc<1,0,0>, cudaFuncAttributeMaxDynamicSharedMemorySize, SMEM_DYN);
    cudaFuncSetAttribute(gemm_tc<0,1,0>, cudaFuncAttributeMaxDynamicSharedMemorySize, SMEM_DYN);

    // tf32-round all first-GEMM operands (hoists cvt out of GEMM hot loops)
    round_tf32_k<<<SEQ * DIM / 1024, 256>>>(x,  X,  SEQ * DIM);
    round_tf32_k<<<DIM * DIM / 1024, 256>>>(wq, Wq, DIM * DIM);
    round_tf32_k<<<DIM * DIM / 1024, 256>>>(wk, Wk, DIM * DIM);
    round_tf32_k<<<DIM * DIM / 1024, 256>>>(wv, Wv, DIM * DIM);

    dim3 gthr(128);                     // GEMM CTAs: 4 warps
    dim3 gproj(DIM / 128, SEQ / 128);   // (8, 64)
    dim3 gsc(SEQ / 128, SEQ / 128);     // (64, 64)

    // QKV projections (Q,K rounded in epilogue; V rounded in transpose)
    gemm_tc<0,0,1><<<gproj, gthr, SMEM_DYN>>>(X, Wq, Q,  DIM, DIM, DIM, DIM, 1.f);
    gemm_tc<0,0,1><<<gproj, gthr, SMEM_DYN>>>(X, Wk, Kp, DIM, DIM, DIM, DIM, 1.f);
    gemm_tc<0,0,0><<<gproj, gthr, SMEM_DYN>>>(X, Wv, V,  DIM, DIM, DIM, DIM, 1.f);

    transpose_rnd<<<dim3(DIM / 32, SEQ / 32), dim3(32, 8)>>>(V, Vt);

    // scores (lower-tri blocks only, diagonal masked)
    gemm_tc<1,0,0><<<gsc, gthr, SMEM_DYN>>>(Q, Kp, S, DIM, DIM, DIM, SEQ, 0.03125f);

    // softmax is written for EXACTLY 256 threads (R5 regression: was launched with 128)
    softmax_rows<<<SEQ, 256>>>(S);

    // out = P @ V = P * Vt^T (both K-major), causal-truncated K per row block
    gemm_tc<0,1,0><<<gproj, gthr, SMEM_DYN>>>(S, Vt, out, 0, SEQ, SEQ, DIM, 1.f);
}

// round 7
// speedup vs baseline: 3.4908x; 1.0171x over previous
#include <cuda_runtime.h>
#include <math.h>
#include <stdint.h>

#define SEQ 8192
#define DIM 1024

// ---- scratch (__device__ globals; no allocs allowed) ----
__device__ float g_Q [SEQ * DIM];
__device__ float g_K [SEQ * DIM];
__device__ float g_V [SEQ * DIM];
__device__ float g_Vt[DIM * SEQ];          // V^T, tf32-rounded (K-major B for PV)
__device__ float g_X [SEQ * DIM];          // x,  tf32-rounded
__device__ float g_Wq[DIM * DIM];
__device__ float g_Wk[DIM * DIM];
__device__ float g_Wv[DIM * DIM];
__device__ float g_S [(size_t)SEQ * SEQ];  // 256MB scores/probs

// ---------------------------------------------------------------------------
__device__ __forceinline__ uint32_t smem_u32(const void* p) {
    uint32_t a;
    asm("{ .reg .u64 t; cvta.to.shared.u64 t, %1; cvt.u32.u64 %0, t; }" : "=r"(a) : "l"(p));
    return a;
}
__device__ __forceinline__ float tf32r(float x) {
    uint32_t r;
    asm("cvt.rna.tf32.f32 %0, %1;" : "=r"(r) : "f"(x));
    return __uint_as_float(r);
}
__device__ __forceinline__ void mma_tf32(float* c, const uint32_t* a, const uint32_t* b) {
    asm volatile(
        "mma.sync.aligned.m16n8k8.row.col.f32.tf32.tf32.f32 "
        "{%0,%1,%2,%3}, {%4,%5,%6,%7}, {%8,%9}, {%0,%1,%2,%3};\n"
        : "+f"(c[0]), "+f"(c[1]), "+f"(c[2]), "+f"(c[3])
        : "r"(a[0]), "r"(a[1]), "r"(a[2]), "r"(a[3]), "r"(b[0]), "r"(b[1]));
}
__device__ __forceinline__ void ldsm4(uint32_t* r, uint32_t addr) {
    asm volatile("ldmatrix.sync.aligned.m8n8.x4.shared.b16 {%0,%1,%2,%3}, [%4];"
                 : "=r"(r[0]), "=r"(r[1]), "=r"(r[2]), "=r"(r[3]) : "r"(addr));
}
#define CP16(dst, src) \
    asm volatile("cp.async.cg.shared.global [%0], [%1], 16;" :: "r"(dst), "l"(src) : "memory")

// ---------------------------------------------------------------------------
// TF32 tensor GEMM: C = A[M,K] * B[N,K]^T (both K-major, values pre-rounded
// to tf32). 128x128 CTA tile, BK=32, 2-stage cp.async double buffer.
// 4 warps, warp tile 64x64 (m16n8k8, 4x8 frags). Fragments via ldmatrix.x4:
// 8 LDSM per 8-K step instead of 32 LDS.32. Row stride 36 words (144B):
// 8 tile rows hit the 8 distinct 16B lanes mod 128B -> conflict-free LDSM.
//   CAUSAL=1: skip bx>by, mask col>row on diagonal tiles
//   KVAR=1  : K = (by+1)*128 (causal-truncated PV)
//   ROUND=1 : tf32-round output (feeds a later MMA)
// ---------------------------------------------------------------------------
template<int CAUSAL, int KVAR, int ROUND>
__global__ void __launch_bounds__(128, 2)
gemm_tc(const float* __restrict__ A, const float* __restrict__ B, float* __restrict__ C,
        int K, int lda, int ldb, int ldc, float scale)
{
    const int bx = blockIdx.x, by = blockIdx.y;
    if (CAUSAL && bx > by) return;
    if (KVAR) K = (by + 1) * 128;
    const int NT = K >> 5;

    extern __shared__ float smem[];              // 2 stages * (A+B) * 128*36
    const uint32_t sbase = smem_u32(smem);
    const int STAGE_B = 2 * 128 * 36 * 4;        // 36864 bytes per stage
    const int BOFF    = 128 * 36 * 4;            // B offset within a stage

    const int tid  = threadIdx.x;
    const int wid  = tid >> 5;
    const int lane = tid & 31;
    const int l4 = lane >> 2, lq = lane & 3;
    const int wm = (wid >> 1) * 64;
    const int wn = (wid & 1) * 64;

    // ldmatrix per-lane addressing (t = tile index 0..3, r = row 0..7)
    const int lt = lane >> 3, lr = lane & 7;
    // A x4 for mi: tiles {rows+0 k0, rows+8 k0, rows+0 k0+4, rows+8 k0+4}
    const uint32_t a_off = (uint32_t)(((wm + (lt & 1) * 8 + lr) * 36 + (lt >> 1) * 4) * 4);
    // B x4 for (ni, ni+1): tiles {ni k0, ni k0+4, ni+1 k0, ni+1 k0+4}
    const uint32_t b_off = (uint32_t)(((wn + (lt >> 1) * 8 + lr) * 36 + (lt & 1) * 4) * 4);

    const float* Ag = A + (size_t)by * 128 * lda;
    const float* Bg = B + (size_t)bx * 128 * ldb;

    float acc[4][8][4];
#pragma unroll
    for (int i = 0; i < 4; i++)
#pragma unroll
        for (int j = 0; j < 8; j++)
#pragma unroll
            for (int e = 0; e < 4; e++) acc[i][j][e] = 0.f;

#define PRODUCE(t) do {                                                       \
        const float* _Ab = Ag + (t) * 32;                                     \
        const float* _Bb = Bg + (t) * 32;                                     \
        const uint32_t _sA = sbase + ((t) & 1) * STAGE_B;                     \
        const uint32_t _sB = _sA + BOFF;                                      \
        _Pragma("unroll")                                                     \
        for (int _j = 0; _j < 8; _j++) {                                      \
            int _q = _j * 128 + tid;                                          \
            int _r = _q >> 3, _c = _q & 7;                                    \
            uint32_t _so = _r * 144 + _c * 16;                                \
            CP16(_sA + _so, _Ab + (size_t)_r * lda + _c * 4);                 \
            CP16(_sB + _so, _Bb + (size_t)_r * ldb + _c * 4);                 \
        }                                                                     \
        asm volatile("cp.async.commit_group;" ::: "memory");                  \
    } while (0)

    PRODUCE(0);
    for (int i = 0; i < NT; i++) {
        if (i + 1 < NT) {
            PRODUCE(i + 1);
            asm volatile("cp.async.wait_group 1;" ::: "memory");
        } else {
            asm volatile("cp.async.wait_group 0;" ::: "memory");
        }
        __syncthreads();

        const uint32_t stA = sbase + (i & 1) * STAGE_B;
        const uint32_t stB = stA + BOFF;

#pragma unroll
        for (int ks = 0; ks < 4; ks++) {
            const uint32_t kbyte = (uint32_t)(ks * 8 * 4);
            uint32_t a[4][4], b[8][2];
#pragma unroll
            for (int mi = 0; mi < 4; mi++)
                ldsm4(a[mi], stA + a_off + (uint32_t)(mi * 16 * 144) + kbyte);
#pragma unroll
            for (int np = 0; np < 4; np++) {
                uint32_t rb[4];
                ldsm4(rb, stB + b_off + (uint32_t)(np * 2 * 8 * 144) + kbyte);
                b[np * 2][0]     = rb[0]; b[np * 2][1]     = rb[1];
                b[np * 2 + 1][0] = rb[2]; b[np * 2 + 1][1] = rb[3];
            }
#pragma unroll
            for (int mi = 0; mi < 4; mi++)
#pragma unroll
                for (int ni = 0; ni < 8; ni++)
                    mma_tf32(acc[mi][ni], a[mi], b[ni]);
        }
        __syncthreads();
    }
#undef PRODUCE

    // ---- epilogue ----
#pragma unroll
    for (int mi = 0; mi < 4; mi++) {
        const int gr0 = by * 128 + wm + mi * 16 + l4;
        const int gr1 = gr0 + 8;
#pragma unroll
        for (int ni = 0; ni < 8; ni++) {
            const int gc = bx * 128 + wn + ni * 8 + 2 * lq;
            float v0 = acc[mi][ni][0] * scale;
            float v1 = acc[mi][ni][1] * scale;
            float v2 = acc[mi][ni][2] * scale;
            float v3 = acc[mi][ni][3] * scale;
            if (CAUSAL && bx == by) {
                if (gc     > gr0) v0 = -1e30f;
                if (gc + 1 > gr0) v1 = -1e30f;
                if (gc     > gr1) v2 = -1e30f;
                if (gc + 1 > gr1) v3 = -1e30f;
            }
            if (ROUND) { v0 = tf32r(v0); v1 = tf32r(v1); v2 = tf32r(v2); v3 = tf32r(v3); }
            *(float2*)(C + (size_t)gr0 * ldc + gc) = make_float2(v0, v1);
            *(float2*)(C + (size_t)gr1 * ldc + gc) = make_float2(v2, v3);
        }
    }
}

// ---------------------------------------------------------------------------
__global__ void __launch_bounds__(256) round_tf32_k(const float* __restrict__ s,
                                                    float* __restrict__ d, int n)
{
    int i = (blockIdx.x * 256 + threadIdx.x) * 4;
    if (i < n) {
        float4 v = *(const float4*)(s + i);
        v.x = tf32r(v.x); v.y = tf32r(v.y); v.z = tf32r(v.z); v.w = tf32r(v.w);
        *(float4*)(d + i) = v;
    }
}

// V[SEQ][DIM] -> Vt[DIM][SEQ], tf32-rounded
__global__ void __launch_bounds__(256) transpose_rnd(const float* __restrict__ src,
                                                     float* __restrict__ dst)
{
    __shared__ float t[32][33];
    const int x = blockIdx.x * 32 + threadIdx.x;
    const int y0 = blockIdx.y * 32;
    for (int j = threadIdx.y; j < 32; j += 8)
        t[j][threadIdx.x] = src[(size_t)(y0 + j) * DIM + x];
    __syncthreads();
    const int xo = y0 + threadIdx.x;
    const int yo0 = blockIdx.x * 32;
    for (int j = threadIdx.y; j < 32; j += 8)
        dst[(size_t)(yo0 + j) * SEQ + xo] = tf32r(t[threadIdx.x][j]);
}

// row softmax over causal prefix; REQUIRES blockDim.x == 256
__global__ void __launch_bounds__(256) softmax_rows(float* __restrict__ S)
{
    __shared__ float buf[SEQ];
    __shared__ float red[256];
    const int row = blockIdx.x;
    const int len = ((row >> 7) + 1) << 7;
    float* Sp = S + (size_t)row * SEQ;
    const int tid = threadIdx.x;

    float lm = -3.4e38f;
    for (int j = tid; j < len; j += 256) { float v = Sp[j]; buf[j] = v; lm = fmaxf(lm, v); }
    red[tid] = lm; __syncthreads();
    for (int s = 128; s > 0; s >>= 1) { if (tid < s) red[tid] = fmaxf(red[tid], red[tid + s]); __syncthreads(); }
    const float m = red[0]; __syncthreads();

    float ls = 0.f;
    for (int j = tid; j < len; j += 256) { float e = __expf(buf[j] - m); buf[j] = e; ls += e; }
    red[tid] = ls; __syncthreads();
    for (int s = 128; s > 0; s >>= 1) { if (tid < s) red[tid] += red[tid + s]; __syncthreads(); }
    const float inv = 1.f / red[0];

    for (int j = tid; j < len; j += 256) Sp[j] = tf32r(buf[j] * inv);
}

// ---------------------------------------------------------------------------
extern "C" void kernel_launch(void* const* d_in, const int* in_sizes, int n_in,
                              void* d_out, int out_size)
{
    const float* x  = (const float*)d_in[0];
    const float* wq = (const float*)d_in[1];
    const float* wk = (const float*)d_in[2];
    const float* wv = (const float*)d_in[3];
    float* out = (float*)d_out;

    float *Q, *Kp, *V, *Vt, *X, *Wq, *Wk, *Wv, *S;
    cudaGetSymbolAddress((void**)&Q,  g_Q);
    cudaGetSymbolAddress((void**)&Kp, g_K);
    cudaGetSymbolAddress((void**)&V,  g_V);
    cudaGetSymbolAddress((void**)&Vt, g_Vt);
    cudaGetSymbolAddress((void**)&X,  g_X);
    cudaGetSymbolAddress((void**)&Wq, g_Wq);
    cudaGetSymbolAddress((void**)&Wk, g_Wk);
    cudaGetSymbolAddress((void**)&Wv, g_Wv);
    cudaGetSymbolAddress((void**)&S,  g_S);

    const int SMEM_DYN = 2 * 2 * 128 * 36 * 4;   // 73728 bytes
    cudaFuncSetAttribute(gemm_tc<0,0,1>, cudaFuncAttributeMaxDynamicSharedMemorySize, SMEM_DYN);
    cudaFuncSetAttribute(gemm_tc<0,0,0>, cudaFuncAttributeMaxDynamicSharedMemorySize, SMEM_DYN);
    cudaFuncSetAttribute(gemm_tc<1,0,0>, cudaFuncAttributeMaxDynamicSharedMemorySize, SMEM_DYN);
    cudaFuncSetAttribute(gemm_tc<0,1,0>, cudaFuncAttributeMaxDynamicSharedMemorySize, SMEM_DYN);

    // tf32-round all first-GEMM operands (hoists cvt out of GEMM hot loops)
    round_tf32_k<<<SEQ * DIM / 1024, 256>>>(x,  X,  SEQ * DIM);
    round_tf32_k<<<DIM * DIM / 1024, 256>>>(wq, Wq, DIM * DIM);
    round_tf32_k<<<DIM * DIM / 1024, 256>>>(wk, Wk, DIM * DIM);
    round_tf32_k<<<DIM * DIM / 1024, 256>>>(wv, Wv, DIM * DIM);

    dim3 gthr(128);
    dim3 gproj(DIM / 128, SEQ / 128);   // (8, 64)
    dim3 gsc(SEQ / 128, SEQ / 128);     // (64, 64)

    gemm_tc<0,0,1><<<gproj, gthr, SMEM_DYN>>>(X, Wq, Q,  DIM, DIM, DIM, DIM, 1.f);
    gemm_tc<0,0,1><<<gproj, gthr, SMEM_DYN>>>(X, Wk, Kp, DIM, DIM, DIM, DIM, 1.f);
    gemm_tc<0,0,0><<<gproj, gthr, SMEM_DYN>>>(X, Wv, V,  DIM, DIM, DIM, DIM, 1.f);

    transpose_rnd<<<dim3(DIM / 32, SEQ / 32), dim3(32, 8)>>>(V, Vt);

    gemm_tc<1,0,0><<<gsc, gthr, SMEM_DYN>>>(Q, Kp, S, DIM, DIM, DIM, SEQ, 0.03125f);

    softmax_rows<<<SEQ, 256>>>(S);

    gemm_tc<0,1,0><<<gproj, gthr, SMEM_DYN>>>(S, Vt, out, 0, SEQ, SEQ, DIM, 1.f);
}

// round 8
// speedup vs baseline: 6.4349x; 1.8434x over previous
#include <cuda_runtime.h>
#include <cuda_fp16.h>
#include <math.h>
#include <stdint.h>

#define SEQ 8192
#define DIM 1024

// ---- scratch (__device__ globals; no allocs allowed) ----
__device__ __half g_hX [SEQ * DIM];
__device__ __half g_hWq[DIM * DIM];
__device__ __half g_hWk[DIM * DIM];
__device__ __half g_hWv[DIM * DIM];
__device__ __half g_hQ [SEQ * DIM];
__device__ __half g_hK [SEQ * DIM];
__device__ __half g_hV [SEQ * DIM];
__device__ __half g_hVt[DIM * SEQ];            // V^T (K-major B for PV)
__device__ float  g_S  [(size_t)SEQ * SEQ];    // fp32 scores (lower-tri blocks)
__device__ __half g_hP [(size_t)SEQ * SEQ];    // fp16 probs

// ---------------------------------------------------------------------------
__device__ __forceinline__ uint32_t smem_u32(const void* p) {
    uint32_t a;
    asm("{ .reg .u64 t; cvta.to.shared.u64 t, %1; cvt.u32.u64 %0, t; }" : "=r"(a) : "l"(p));
    return a;
}
__device__ __forceinline__ void mma_f16(float* c, const uint32_t* a, const uint32_t* b) {
    asm volatile(
        "mma.sync.aligned.m16n8k16.row.col.f32.f16.f16.f32 "
        "{%0,%1,%2,%3}, {%4,%5,%6,%7}, {%8,%9}, {%0,%1,%2,%3};\n"
        : "+f"(c[0]), "+f"(c[1]), "+f"(c[2]), "+f"(c[3])
        : "r"(a[0]), "r"(a[1]), "r"(a[2]), "r"(a[3]), "r"(b[0]), "r"(b[1]));
}
__device__ __forceinline__ void ldsm4(uint32_t* r, uint32_t addr) {
    asm volatile("ldmatrix.sync.aligned.m8n8.x4.shared.b16 {%0,%1,%2,%3}, [%4];"
                 : "=r"(r[0]), "=r"(r[1]), "=r"(r[2]), "=r"(r[3]) : "r"(addr));
}
#define CP16(dst, src) \
    asm volatile("cp.async.cg.shared.global [%0], [%1], 16;" :: "r"(dst), "l"(src) : "memory")

// ---------------------------------------------------------------------------
// FP16 tensor GEMM, fp32 accumulate: C = A[M,K] * B[N,K]^T (K-major half).
// 128x128 CTA tile, BK=32, 2-stage cp.async double buffer, 4 warps,
// warp tile 64x64 (m16n8k16: 4x8 frags, 32 MMA + 8 LDSM per 16-K step).
// smem row stride 40 halves (80B): rows 0..7 -> 16B lanes {0,80,32,112,64,
// 16,96,48} mod 128 -> conflict-free ldmatrix.
//   CAUSAL=1: skip bx>by, mask col>row on diagonal tiles
//   KVAR=1  : K = (by+1)*128 (causal-truncated PV)
//   OUTH=1  : store C as half (feeds a later MMA); else float
// ---------------------------------------------------------------------------
template<int CAUSAL, int KVAR, int OUTH>
__global__ void __launch_bounds__(128, 2)
gemm_h(const __half* __restrict__ A, const __half* __restrict__ B, void* __restrict__ Cv,
       int K, int lda, int ldb, int ldc, float scale)
{
    const int bx = blockIdx.x, by = blockIdx.y;
    if (CAUSAL && bx > by) return;
    if (KVAR) K = (by + 1) * 128;
    const int NT = K >> 5;

    extern __shared__ __half smem[];             // 2 stages * (A+B) * 128*40 halves
    const uint32_t sbase = smem_u32(smem);
    const int STAGE_B = 2 * 128 * 40 * 2;        // 20480 bytes per stage
    const int BOFF    = 128 * 40 * 2;            // 10240: B offset within stage

    const int tid  = threadIdx.x;
    const int wid  = tid >> 5;
    const int lane = tid & 31;
    const int l4 = lane >> 2, lq = lane & 3;
    const int wm = (wid >> 1) * 64;
    const int wn = (wid & 1) * 64;

    // ldmatrix lane addressing (lt = tile 0..3, lr = row 0..7), stride 80B
    const int lt = lane >> 3, lr = lane & 7;
    // A x4 -> {m+0 k0, m+8 k0, m+0 k8, m+8 k8}
    const uint32_t a_off = (uint32_t)((wm + (lt & 1) * 8 + lr) * 80 + (lt >> 1) * 16);
    // B x4 -> {n+0 k0, n+0 k8, n+8 k0, n+8 k8}
    const uint32_t b_off = (uint32_t)((wn + (lt >> 1) * 8 + lr) * 80 + (lt & 1) * 16);

    const __half* Ag = A + (size_t)by * 128 * lda;
    const __half* Bg = B + (size_t)bx * 128 * ldb;

    float acc[4][8][4];
#pragma unroll
    for (int i = 0; i < 4; i++)
#pragma unroll
        for (int j = 0; j < 8; j++)
#pragma unroll
            for (int e = 0; e < 4; e++) acc[i][j][e] = 0.f;

    // stage filler: 128 rows x 32 halves (4x16B granules per row) for A and B
#define PRODUCE(t) do {                                                       \
        const __half* _Ab = Ag + (t) * 32;                                    \
        const __half* _Bb = Bg + (t) * 32;                                    \
        const uint32_t _sA = sbase + ((t) & 1) * STAGE_B;                     \
        const uint32_t _sB = _sA + BOFF;                                      \
        _Pragma("unroll")                                                     \
        for (int _j = 0; _j < 4; _j++) {                                      \
            int _q = _j * 128 + tid;                                          \
            int _r = _q >> 2, _c = _q & 3;                                    \
            uint32_t _so = _r * 80 + _c * 16;                                 \
            CP16(_sA + _so, _Ab + (size_t)_r * lda + _c * 8);                 \
            CP16(_sB + _so, _Bb + (size_t)_r * ldb + _c * 8);                 \
        }                                                                     \
        asm volatile("cp.async.commit_group;" ::: "memory");                  \
    } while (0)

    PRODUCE(0);
    for (int i = 0; i < NT; i++) {
        if (i + 1 < NT) {
            PRODUCE(i + 1);
            asm volatile("cp.async.wait_group 1;" ::: "memory");
        } else {
            asm volatile("cp.async.wait_group 0;" ::: "memory");
        }
        __syncthreads();

        const uint32_t stA = sbase + (i & 1) * STAGE_B;
        const uint32_t stB = stA + BOFF;

#pragma unroll
        for (int ks = 0; ks < 2; ks++) {         // two 16-K steps per 32-K tile
            const uint32_t kbyte = (uint32_t)(ks * 32);
            uint32_t a[4][4], b[8][2];
#pragma unroll
            for (int mi = 0; mi < 4; mi++)
                ldsm4(a[mi], stA + a_off + (uint32_t)(mi * 16 * 80) + kbyte);
#pragma unroll
            for (int np = 0; np < 4; np++) {
                uint32_t rb[4];
                ldsm4(rb, stB + b_off + (uint32_t)(np * 16 * 80) + kbyte);
                b[np * 2][0]     = rb[0]; b[np * 2][1]     = rb[1];
                b[np * 2 + 1][0] = rb[2]; b[np * 2 + 1][1] = rb[3];
            }
#pragma unroll
            for (int mi = 0; mi < 4; mi++)
#pragma unroll
                for (int ni = 0; ni < 8; ni++)
                    mma_f16(acc[mi][ni], a[mi], b[ni]);
        }
        __syncthreads();
    }
#undef PRODUCE

    // ---- epilogue (C layout of m16n8: rows l4/l4+8, cols 2*lq) ----
#pragma unroll
    for (int mi = 0; mi < 4; mi++) {
        const int gr0 = by * 128 + wm + mi * 16 + l4;
        const int gr1 = gr0 + 8;
#pragma unroll
        for (int ni = 0; ni < 8; ni++) {
            const int gc = bx * 128 + wn + ni * 8 + 2 * lq;
            float v0 = acc[mi][ni][0] * scale;
            float v1 = acc[mi][ni][1] * scale;
            float v2 = acc[mi][ni][2] * scale;
            float v3 = acc[mi][ni][3] * scale;
            if (CAUSAL && bx == by) {
                if (gc     > gr0) v0 = -1e30f;
                if (gc + 1 > gr0) v1 = -1e30f;
                if (gc     > gr1) v2 = -1e30f;
                if (gc + 1 > gr1) v3 = -1e30f;
            }
            if (OUTH) {
                __half* C = (__half*)Cv;
                *(__half2*)(C + (size_t)gr0 * ldc + gc) = __floats2half2_rn(v0, v1);
                *(__half2*)(C + (size_t)gr1 * ldc + gc) = __floats2half2_rn(v2, v3);
            } else {
                float* C = (float*)Cv;
                *(float2*)(C + (size_t)gr0 * ldc + gc) = make_float2(v0, v1);
                *(float2*)(C + (size_t)gr1 * ldc + gc) = make_float2(v2, v3);
            }
        }
    }
}

// ---------------------------------------------------------------------------
__global__ void __launch_bounds__(256) f2h_k(const float* __restrict__ s,
                                             __half* __restrict__ d, int n)
{
    int i = (blockIdx.x * 256 + threadIdx.x) * 4;
    if (i < n) {
        float4 v = *(const float4*)(s + i);
        __half2 h0 = __floats2half2_rn(v.x, v.y);
        __half2 h1 = __floats2half2_rn(v.z, v.w);
        *(__half2*)(d + i)     = h0;
        *(__half2*)(d + i + 2) = h1;
    }
}

// V[SEQ][DIM] half -> Vt[DIM][SEQ] half
__global__ void __launch_bounds__(256) transpose_h(const __half* __restrict__ src,
                                                   __half* __restrict__ dst)
{
    __shared__ __half t[32][33];
    const int x = blockIdx.x * 32 + threadIdx.x;
    const int y0 = blockIdx.y * 32;
    for (int j = threadIdx.y; j < 32; j += 8)
        t[j][threadIdx.x] = src[(size_t)(y0 + j) * DIM + x];
    __syncthreads();
    const int xo = y0 + threadIdx.x;
    const int yo0 = blockIdx.x * 32;
    for (int j = threadIdx.y; j < 32; j += 8)
        dst[(size_t)(yo0 + j) * SEQ + xo] = t[threadIdx.x][j];
}

// row softmax over causal prefix: float in, half out. REQUIRES 256 threads.
__global__ void __launch_bounds__(256) softmax_rows(const float* __restrict__ S,
                                                    __half* __restrict__ P)
{
    __shared__ float buf[SEQ];
    __shared__ float red[256];
    const int row = blockIdx.x;
    const int len = ((row >> 7) + 1) << 7;
    const float* Sp = S + (size_t)row * SEQ;
    __half* Pp = P + (size_t)row * SEQ;
    const int tid = threadIdx.x;

    float lm = -3.4e38f;
    for (int j = tid; j < len; j += 256) { float v = Sp[j]; buf[j] = v; lm = fmaxf(lm, v); }
    red[tid] = lm; __syncthreads();
    for (int s = 128; s > 0; s >>= 1) { if (tid < s) red[tid] = fmaxf(red[tid], red[tid + s]); __syncthreads(); }
    const float m = red[0]; __syncthreads();

    float ls = 0.f;
    for (int j = tid; j < len; j += 256) { float e = __expf(buf[j] - m); buf[j] = e; ls += e; }
    red[tid] = ls; __syncthreads();
    for (int s = 128; s > 0; s >>= 1) { if (tid < s) red[tid] += red[tid + s]; __syncthreads(); }
    const float inv = 1.f / red[0];

    for (int j = tid; j < len; j += 256) Pp[j] = __float2half_rn(buf[j] * inv);
}

// ---------------------------------------------------------------------------
extern "C" void kernel_launch(void* const* d_in, const int* in_sizes, int n_in,
                              void* d_out, int out_size)
{
    const float* x  = (const float*)d_in[0];
    const float* wq = (const float*)d_in[1];
    const float* wk = (const float*)d_in[2];
    const float* wv = (const float*)d_in[3];
    float* out = (float*)d_out;

    __half *hX, *hWq, *hWk, *hWv, *hQ, *hK, *hV, *hVt, *hP;
    float* S;
    cudaGetSymbolAddress((void**)&hX,  g_hX);
    cudaGetSymbolAddress((void**)&hWq, g_hWq);
    cudaGetSymbolAddress((void**)&hWk, g_hWk);
    cudaGetSymbolAddress((void**)&hWv, g_hWv);
    cudaGetSymbolAddress((void**)&hQ,  g_hQ);
    cudaGetSymbolAddress((void**)&hK,  g_hK);
    cudaGetSymbolAddress((void**)&hV,  g_hV);
    cudaGetSymbolAddress((void**)&hVt, g_hVt);
    cudaGetSymbolAddress((void**)&hP,  g_hP);
    cudaGetSymbolAddress((void**)&S,   g_S);

    const int SMEM_DYN = 2 * 2 * 128 * 40 * 2;   // 40960 bytes
    cudaFuncSetAttribute(gemm_h<0,0,1>, cudaFuncAttributeMaxDynamicSharedMemorySize, SMEM_DYN);
    cudaFuncSetAttribute(gemm_h<1,0,0>, cudaFuncAttributeMaxDynamicSharedMemorySize, SMEM_DYN);
    cudaFuncSetAttribute(gemm_h<0,1,0>, cudaFuncAttributeMaxDynamicSharedMemorySize, SMEM_DYN);

    // convert operands to fp16 (2^-11 rounding, same as tf32)
    f2h_k<<<SEQ * DIM / 1024, 256>>>(x,  hX,  SEQ * DIM);
    f2h_k<<<DIM * DIM / 1024, 256>>>(wq, hWq, DIM * DIM);
    f2h_k<<<DIM * DIM / 1024, 256>>>(wk, hWk, DIM * DIM);
    f2h_k<<<DIM * DIM / 1024, 256>>>(wv, hWv, DIM * DIM);

    dim3 gthr(128);
    dim3 gproj(DIM / 128, SEQ / 128);   // (8, 64)
    dim3 gsc(SEQ / 128, SEQ / 128);     // (64, 64)

    // QKV projections -> half
    gemm_h<0,0,1><<<gproj, gthr, SMEM_DYN>>>(hX, hWq, hQ, DIM, DIM, DIM, DIM, 1.f);
    gemm_h<0,0,1><<<gproj, gthr, SMEM_DYN>>>(hX, hWk, hK, DIM, DIM, DIM, DIM, 1.f);
    gemm_h<0,0,1><<<gproj, gthr, SMEM_DYN>>>(hX, hWv, hV, DIM, DIM, DIM, DIM, 1.f);

    transpose_h<<<dim3(DIM / 32, SEQ / 32), dim3(32, 8)>>>(hV, hVt);

    // scores (float, lower-tri blocks only, diagonal masked)
    gemm_h<1,0,0><<<gsc, gthr, SMEM_DYN>>>(hQ, hK, S, DIM, DIM, DIM, SEQ, 0.03125f);

    softmax_rows<<<SEQ, 256>>>(S, hP);

    // out = P @ V = P * Vt^T, causal-truncated K per row block
    gemm_h<0,1,0><<<gproj, gthr, SMEM_DYN>>>(hP, hVt, out, 0, SEQ, SEQ, DIM, 1.f);
}

// round 10
// speedup vs baseline: 6.7048x; 1.0419x over previous
#include <cuda_runtime.h>
#include <cuda_fp16.h>
#include <math.h>
#include <stdint.h>

#define SEQ 8192
#define DIM 1024

// ---- scratch (__device__ globals; no allocs allowed) ----
__device__ __half g_hX [SEQ * DIM];
__device__ __half g_hWq[DIM * DIM];
__device__ __half g_hWk[DIM * DIM];
__device__ __half g_hWv[DIM * DIM];
__device__ __half g_hQ [SEQ * DIM];
__device__ __half g_hK [SEQ * DIM];
__device__ __half g_hV [SEQ * DIM];
__device__ __half g_hVt[DIM * SEQ];            // V^T (K-major B for PV)
__device__ float  g_S  [(size_t)SEQ * SEQ];    // fp32 scores (lower-tri blocks)
__device__ __half g_hP [(size_t)SEQ * SEQ];    // fp16 probs

// ---------------------------------------------------------------------------
__device__ __forceinline__ uint32_t smem_u32(const void* p) {
    uint32_t a;
    asm("{ .reg .u64 t; cvta.to.shared.u64 t, %1; cvt.u32.u64 %0, t; }" : "=r"(a) : "l"(p));
    return a;
}
__device__ __forceinline__ void mma_f16(float* c, const uint32_t* a, const uint32_t* b) {
    asm volatile(
        "mma.sync.aligned.m16n8k16.row.col.f32.f16.f16.f32 "
        "{%0,%1,%2,%3}, {%4,%5,%6,%7}, {%8,%9}, {%0,%1,%2,%3};\n"
        : "+f"(c[0]), "+f"(c[1]), "+f"(c[2]), "+f"(c[3])
        : "r"(a[0]), "r"(a[1]), "r"(a[2]), "r"(a[3]), "r"(b[0]), "r"(b[1]));
}
__device__ __forceinline__ void ldsm4(uint32_t* r, uint32_t addr) {
    asm volatile("ldmatrix.sync.aligned.m8n8.x4.shared.b16 {%0,%1,%2,%3}, [%4];"
                 : "=r"(r[0]), "=r"(r[1]), "=r"(r[2]), "=r"(r[3]) : "r"(addr));
}
#define CP16(dst, src) \
    asm volatile("cp.async.cg.shared.global [%0], [%1], 16;" :: "r"(dst), "l"(src) : "memory")

// ---------------------------------------------------------------------------
// FP16 tensor GEMM, fp32 accumulate: C = A[M,K] * B[N,K]^T (K-major half).
// 128x128 CTA tile, BK=32, 4-stage cp.async pipeline, ONE __syncthreads per
// tile with the CORRECT publication order:
//     wait_group 2  -> group i complete (thread-local)
//     __syncthreads -> stage i CTA-visible AND stage (i-1) reads all done
//     PRODUCE(i+3)  -> overwrites stage (i-1)&3, now provably safe
//     consume stage i
// Tail commits empty groups so the constant wait count stays exact.
// 4 warps, warp tile 64x64 (m16n8k16: 4x8 frags, 32 MMA + 8 LDSM / 16-K).
// smem row stride 40 halves (80B) -> conflict-free ldmatrix.
//   CAUSAL=1: skip bx>by, mask col>row on diagonal tiles
//   KVAR=1  : K = (by+1)*128 (causal-truncated PV)
//   OUTH=1  : store C as half (feeds a later MMA); else float
// ---------------------------------------------------------------------------
template<int CAUSAL, int KVAR, int OUTH>
__global__ void __launch_bounds__(128, 2)
gemm_h(const __half* __restrict__ A, const __half* __restrict__ B, void* __restrict__ Cv,
       int K, int lda, int ldb, int ldc, float scale)
{
    const int bx = blockIdx.x, by = blockIdx.y;
    if (CAUSAL && bx > by) return;
    if (KVAR) K = (by + 1) * 128;
    const int NT = K >> 5;                       // >= 4 always (K >= 128)

    extern __shared__ __half smem[];             // 4 stages * (A+B) * 128*40 halves
    const uint32_t sbase = smem_u32(smem);
    const int STAGE_B = 2 * 128 * 40 * 2;        // 20480 bytes per stage
    const int BOFF    = 128 * 40 * 2;

    const int tid  = threadIdx.x;
    const int wid  = tid >> 5;
    const int lane = tid & 31;
    const int l4 = lane >> 2, lq = lane & 3;
    const int wm = (wid >> 1) * 64;
    const int wn = (wid & 1) * 64;

    const int lt = lane >> 3, lr = lane & 7;
    const uint32_t a_off = (uint32_t)((wm + (lt & 1) * 8 + lr) * 80 + (lt >> 1) * 16);
    const uint32_t b_off = (uint32_t)((wn + (lt >> 1) * 8 + lr) * 80 + (lt & 1) * 16);

    const __half* Ag = A + (size_t)by * 128 * lda;
    const __half* Bg = B + (size_t)bx * 128 * ldb;

    float acc[4][8][4];
#pragma unroll
    for (int i = 0; i < 4; i++)
#pragma unroll
        for (int j = 0; j < 8; j++)
#pragma unroll
            for (int e = 0; e < 4; e++) acc[i][j][e] = 0.f;

#define PRODUCE(t) do {                                                       \
        const __half* _Ab = Ag + (t) * 32;                                    \
        const __half* _Bb = Bg + (t) * 32;                                    \
        const uint32_t _sA = sbase + ((t) & 3) * STAGE_B;                     \
        const uint32_t _sB = _sA + BOFF;                                      \
        _Pragma("unroll")                                                     \
        for (int _j = 0; _j < 4; _j++) {                                      \
            int _q = _j * 128 + tid;                                          \
            int _r = _q >> 2, _c = _q & 3;                                    \
            uint32_t _so = _r * 80 + _c * 16;                                 \
            CP16(_sA + _so, _Ab + (size_t)_r * lda + _c * 8);                 \
            CP16(_sB + _so, _Bb + (size_t)_r * ldb + _c * 8);                 \
        }                                                                     \
        asm volatile("cp.async.commit_group;" ::: "memory");                  \
    } while (0)

    // prologue: groups 0,1,2 pending
    PRODUCE(0); PRODUCE(1); PRODUCE(2);

    for (int i = 0; i < NT; i++) {
        asm volatile("cp.async.wait_group 2;" ::: "memory");   // group i done (this thread)
        __syncthreads();                                       // publish stage i; stage i-1 reads done
        if (i + 3 < NT) PRODUCE(i + 3);                        // overwrite stage (i-1)&3
        else asm volatile("cp.async.commit_group;" ::: "memory");  // keep count exact

        const uint32_t stA = sbase + (i & 3) * STAGE_B;
        const uint32_t stB = stA + BOFF;

#pragma unroll
        for (int ks = 0; ks < 2; ks++) {
            const uint32_t kbyte = (uint32_t)(ks * 32);
            uint32_t a[4][4], b[8][2];
#pragma unroll
            for (int mi = 0; mi < 4; mi++)
                ldsm4(a[mi], stA + a_off + (uint32_t)(mi * 16 * 80) + kbyte);
#pragma unroll
            for (int np = 0; np < 4; np++) {
                uint32_t rb[4];
                ldsm4(rb, stB + b_off + (uint32_t)(np * 16 * 80) + kbyte);
                b[np * 2][0]     = rb[0]; b[np * 2][1]     = rb[1];
                b[np * 2 + 1][0] = rb[2]; b[np * 2 + 1][1] = rb[3];
            }
#pragma unroll
            for (int mi = 0; mi < 4; mi++)
#pragma unroll
                for (int ni = 0; ni < 8; ni++)
                    mma_f16(acc[mi][ni], a[mi], b[ni]);
        }
    }
#undef PRODUCE

    // ---- epilogue (C layout of m16n8: rows l4/l4+8, cols 2*lq) ----
#pragma unroll
    for (int mi = 0; mi < 4; mi++) {
        const int gr0 = by * 128 + wm + mi * 16 + l4;
        const int gr1 = gr0 + 8;
#pragma unroll
        for (int ni = 0; ni < 8; ni++) {
            const int gc = bx * 128 + wn + ni * 8 + 2 * lq;
            float v0 = acc[mi][ni][0] * scale;
            float v1 = acc[mi][ni][1] * scale;
            float v2 = acc[mi][ni][2] * scale;
            float v3 = acc[mi][ni][3] * scale;
            if (CAUSAL && bx == by) {
                if (gc     > gr0) v0 = -1e30f;
                if (gc + 1 > gr0) v1 = -1e30f;
                if (gc     > gr1) v2 = -1e30f;
                if (gc + 1 > gr1) v3 = -1e30f;
            }
            if (OUTH) {
                __half* C = (__half*)Cv;
                *(__half2*)(C + (size_t)gr0 * ldc + gc) = __floats2half2_rn(v0, v1);
                *(__half2*)(C + (size_t)gr1 * ldc + gc) = __floats2half2_rn(v2, v3);
            } else {
                float* C = (float*)Cv;
                *(float2*)(C + (size_t)gr0 * ldc + gc) = make_float2(v0, v1);
                *(float2*)(C + (size_t)gr1 * ldc + gc) = make_float2(v2, v3);
            }
        }
    }
}

// ---------------------------------------------------------------------------
// single-launch fp32 -> fp16 conversion of x + the three weights
__global__ void __launch_bounds__(256)
conv_all(const float* __restrict__ x,  const float* __restrict__ wq,
         const float* __restrict__ wk, const float* __restrict__ wv,
         __half* __restrict__ hX,  __half* __restrict__ hWq,
         __half* __restrict__ hWk, __half* __restrict__ hWv)
{
    const long long NX = (long long)SEQ * DIM / 4;
    const long long NW = (long long)DIM * DIM / 4;
    long long f4 = (long long)blockIdx.x * 256 + threadIdx.x;
    const float* s; __half* d; long long off;
    if      (f4 < NX)          { s = x;  d = hX;  off = f4; }
    else if (f4 < NX + NW)     { s = wq; d = hWq; off = f4 - NX; }
    else if (f4 < NX + 2 * NW) { s = wk; d = hWk; off = f4 - NX - NW; }
    else                       { s = wv; d = hWv; off = f4 - NX - 2 * NW; }
    float4 v = *(const float4*)(s + off * 4);
    *(__half2*)(d + off * 4)     = __floats2half2_rn(v.x, v.y);
    *(__half2*)(d + off * 4 + 2) = __floats2half2_rn(v.z, v.w);
}

// V[SEQ][DIM] half -> Vt[DIM][SEQ] half
__global__ void __launch_bounds__(256) transpose_h(const __half* __restrict__ src,
                                                   __half* __restrict__ dst)
{
    __shared__ __half t[32][33];
    const int x = blockIdx.x * 32 + threadIdx.x;
    const int y0 = blockIdx.y * 32;
    for (int j = threadIdx.y; j < 32; j += 8)
        t[j][threadIdx.x] = src[(size_t)(y0 + j) * DIM + x];
    __syncthreads();
    const int xo = y0 + threadIdx.x;
    const int yo0 = blockIdx.x * 32;
    for (int j = threadIdx.y; j < 32; j += 8)
        dst[(size_t)(yo0 + j) * SEQ + xo] = t[threadIdx.x][j];
}

// row softmax over causal prefix: float in, half out. REQUIRES 256 threads.
__global__ void __launch_bounds__(256) softmax_rows(const float* __restrict__ S,
                                                    __half* __restrict__ P)
{
    __shared__ float buf[SEQ];
    __shared__ float red[256];
    const int row = blockIdx.x;
    const int len = ((row >> 7) + 1) << 7;
    const float* Sp = S + (size_t)row * SEQ;
    __half* Pp = P + (size_t)row * SEQ;
    const int tid = threadIdx.x;

    float lm = -3.4e38f;
    for (int j = tid; j < len; j += 256) { float v = Sp[j]; buf[j] = v; lm = fmaxf(lm, v); }
    red[tid] = lm; __syncthreads();
    for (int s = 128; s > 0; s >>= 1) { if (tid < s) red[tid] = fmaxf(red[tid], red[tid + s]); __syncthreads(); }
    const float m = red[0]; __syncthreads();

    float ls = 0.f;
    for (int j = tid; j < len; j += 256) { float e = __expf(buf[j] - m); buf[j] = e; ls += e; }
    red[tid] = ls; __syncthreads();
    for (int s = 128; s > 0; s >>= 1) { if (tid < s) red[tid] += red[tid + s]; __syncthreads(); }
    const float inv = 1.f / red[0];

    for (int j = tid; j < len; j += 256) Pp[j] = __float2half_rn(buf[j] * inv);
}

// ---------------------------------------------------------------------------
extern "C" void kernel_launch(void* const* d_in, const int* in_sizes, int n_in,
                              void* d_out, int out_size)
{
    const float* x  = (const float*)d_in[0];
    const float* wq = (const float*)d_in[1];
    const float* wk = (const float*)d_in[2];
    const float* wv = (const float*)d_in[3];
    float* out = (float*)d_out;

    __half *hX, *hWq, *hWk, *hWv, *hQ, *hK, *hV, *hVt, *hP;
    float* S;
    cudaGetSymbolAddress((void**)&hX,  g_hX);
    cudaGetSymbolAddress((void**)&hWq, g_hWq);
    cudaGetSymbolAddress((void**)&hWk, g_hWk);
    cudaGetSymbolAddress((void**)&hWv, g_hWv);
    cudaGetSymbolAddress((void**)&hQ,  g_hQ);
    cudaGetSymbolAddress((void**)&hK,  g_hK);
    cudaGetSymbolAddress((void**)&hV,  g_hV);
    cudaGetSymbolAddress((void**)&hVt, g_hVt);
    cudaGetSymbolAddress((void**)&hP,  g_hP);
    cudaGetSymbolAddress((void**)&S,   g_S);

    const int SMEM_DYN = 4 * 2 * 128 * 40 * 2;   // 81920 bytes (4 stages)
    cudaFuncSetAttribute(gemm_h<0,0,1>, cudaFuncAttributeMaxDynamicSharedMemorySize, SMEM_DYN);
    cudaFuncSetAttribute(gemm_h<1,0,0>, cudaFuncAttributeMaxDynamicSharedMemorySize, SMEM_DYN);
    cudaFuncSetAttribute(gemm_h<0,1,0>, cudaFuncAttributeMaxDynamicSharedMemorySize, SMEM_DYN);

    const long long NCONV = (long long)SEQ * DIM / 4 + 3LL * DIM * DIM / 4;
    conv_all<<<(unsigned)((NCONV + 255) / 256), 256>>>(x, wq, wk, wv, hX, hWq, hWk, hWv);

    dim3 gthr(128);
    dim3 gproj(DIM / 128, SEQ / 128);   // (8, 64)
    dim3 gsc(SEQ / 128, SEQ / 128);     // (64, 64)

    gemm_h<0,0,1><<<gproj, gthr, SMEM_DYN>>>(hX, hWq, hQ, DIM, DIM, DIM, DIM, 1.f);
    gemm_h<0,0,1><<<gproj, gthr, SMEM_DYN>>>(hX, hWk, hK, DIM, DIM, DIM, DIM, 1.f);
    gemm_h<0,0,1><<<gproj, gthr, SMEM_DYN>>>(hX, hWv, hV, DIM, DIM, DIM, DIM, 1.f);

    transpose_h<<<dim3(DIM / 32, SEQ / 32), dim3(32, 8)>>>(hV, hVt);

    gemm_h<1,0,0><<<gsc, gthr, SMEM_DYN>>>(hQ, hK, S, DIM, DIM, DIM, SEQ, 0.03125f);

    softmax_rows<<<SEQ, 256>>>(S, hP);

    gemm_h<0,1,0><<<gproj, gthr, SMEM_DYN>>>(hP, hVt, out, 0, SEQ, SEQ, DIM, 1.f);
}

// round 11
// speedup vs baseline: 7.0430x; 1.0504x over previous
#include <cuda_runtime.h>
#include <cuda_fp16.h>
#include <math.h>
#include <stdint.h>

#define SEQ 8192
#define DIM 1024

// ---- scratch (__device__ globals; no allocs allowed) ----
__device__ __half g_hX [SEQ * DIM];
__device__ __half g_hWq[DIM * DIM];
__device__ __half g_hWk[DIM * DIM];
__device__ __half g_hWv[DIM * DIM];
__device__ __half g_hQ [SEQ * DIM];
__device__ __half g_hK [SEQ * DIM];
__device__ __half g_hV [SEQ * DIM];
__device__ __half g_hVt[DIM * SEQ];            // V^T (K-major B for PV)
__device__ __half g_hP [(size_t)SEQ * SEQ];    // unscaled exp(s - m_b), half
__device__ float  g_Mb [(size_t)SEQ * 64];     // per (row, block) max
__device__ float  g_Lb [(size_t)SEQ * 64];     // per (row, block) sum
__device__ __half g_sc [(size_t)SEQ * 64];     // per (row, block) scale e^{mb-m}/L

// ---------------------------------------------------------------------------
__device__ __forceinline__ uint32_t smem_u32(const void* p) {
    uint32_t a;
    asm("{ .reg .u64 t; cvta.to.shared.u64 t, %1; cvt.u32.u64 %0, t; }" : "=r"(a) : "l"(p));
    return a;
}
__device__ __forceinline__ void mma_f16(float* c, const uint32_t* a, const uint32_t* b) {
    asm volatile(
        "mma.sync.aligned.m16n8k16.row.col.f32.f16.f16.f32 "
        "{%0,%1,%2,%3}, {%4,%5,%6,%7}, {%8,%9}, {%0,%1,%2,%3};\n"
        : "+f"(c[0]), "+f"(c[1]), "+f"(c[2]), "+f"(c[3])
        : "r"(a[0]), "r"(a[1]), "r"(a[2]), "r"(a[3]), "r"(b[0]), "r"(b[1]));
}
__device__ __forceinline__ void ldsm4(uint32_t* r, uint32_t addr) {
    asm volatile("ldmatrix.sync.aligned.m8n8.x4.shared.b16 {%0,%1,%2,%3}, [%4];"
                 : "=r"(r[0]), "=r"(r[1]), "=r"(r[2]), "=r"(r[3]) : "r"(addr));
}
__device__ __forceinline__ uint32_t hmul2_u(uint32_t a, __half2 s) {
    __half2 v = *(__half2*)&a;
    v = __hmul2(v, s);
    return *(uint32_t*)&v;
}
#define CP16(dst, src) \
    asm volatile("cp.async.cg.shared.global [%0], [%1], 16;" :: "r"(dst), "l"(src) : "memory")

// shared mainloop constants
#define STAGE_B (2 * 128 * 40 * 2)   // 20480 bytes per stage
#define BOFF    (128 * 40 * 2)

// stage filler macro (expects Ag,Bg,lda,ldb,sbase,tid in scope)
#define PRODUCE(t) do {                                                       \
        const __half* _Ab = Ag + (t) * 32;                                    \
        const __half* _Bb = Bg + (t) * 32;                                    \
        const uint32_t _sA = sbase + ((t) & 3) * STAGE_B;                     \
        const uint32_t _sB = _sA + BOFF;                                      \
        _Pragma("unroll")                                                     \
        for (int _j = 0; _j < 4; _j++) {                                      \
            int _q = _j * 128 + tid;                                          \
            int _r = _q >> 2, _c = _q & 3;                                    \
            uint32_t _so = _r * 80 + _c * 16;                                 \
            CP16(_sA + _so, _Ab + (size_t)_r * lda + _c * 8);                 \
            CP16(_sB + _so, _Bb + (size_t)_r * ldb + _c * 8);                 \
        }                                                                     \
        asm volatile("cp.async.commit_group;" ::: "memory");                  \
    } while (0)

// ---------------------------------------------------------------------------
// Plain FP16 GEMM (projections): C = A[M,K]*B[N,K]^T, half out.
// 128x128 tile, BK=32, 4-stage pipeline, one sync per tile (R10-proven).
// ---------------------------------------------------------------------------
__global__ void __launch_bounds__(128, 2)
gemm_h(const __half* __restrict__ A, const __half* __restrict__ B,
       __half* __restrict__ C, int K, int lda, int ldb, int ldc)
{
    const int bx = blockIdx.x, by = blockIdx.y;
    const int NT = K >> 5;

    extern __shared__ __half smem[];
    const uint32_t sbase = smem_u32(smem);
    const int tid = threadIdx.x, wid = tid >> 5, lane = tid & 31;
    const int l4 = lane >> 2, lq = lane & 3;
    const int wm = (wid >> 1) * 64, wn = (wid & 1) * 64;
    const int lt = lane >> 3, lr = lane & 7;
    const uint32_t a_off = (uint32_t)((wm + (lt & 1) * 8 + lr) * 80 + (lt >> 1) * 16);
    const uint32_t b_off = (uint32_t)((wn + (lt >> 1) * 8 + lr) * 80 + (lt & 1) * 16);

    const __half* Ag = A + (size_t)by * 128 * lda;
    const __half* Bg = B + (size_t)bx * 128 * ldb;

    float acc[4][8][4];
#pragma unroll
    for (int i = 0; i < 4; i++)
#pragma unroll
        for (int j = 0; j < 8; j++)
#pragma unroll
            for (int e = 0; e < 4; e++) acc[i][j][e] = 0.f;

    PRODUCE(0); PRODUCE(1); PRODUCE(2);
    for (int i = 0; i < NT; i++) {
        asm volatile("cp.async.wait_group 2;" ::: "memory");
        __syncthreads();
        if (i + 3 < NT) PRODUCE(i + 3);
        else asm volatile("cp.async.commit_group;" ::: "memory");

        const uint32_t stA = sbase + (i & 3) * STAGE_B;
        const uint32_t stB = stA + BOFF;
#pragma unroll
        for (int ks = 0; ks < 2; ks++) {
            const uint32_t kbyte = (uint32_t)(ks * 32);
            uint32_t a[4][4], b[8][2];
#pragma unroll
            for (int mi = 0; mi < 4; mi++)
                ldsm4(a[mi], stA + a_off + (uint32_t)(mi * 16 * 80) + kbyte);
#pragma unroll
            for (int np = 0; np < 4; np++) {
                uint32_t rb[4];
                ldsm4(rb, stB + b_off + (uint32_t)(np * 16 * 80) + kbyte);
                b[np*2][0] = rb[0]; b[np*2][1] = rb[1];
                b[np*2+1][0] = rb[2]; b[np*2+1][1] = rb[3];
            }
#pragma unroll
            for (int mi = 0; mi < 4; mi++)
#pragma unroll
                for (int ni = 0; ni < 8; ni++)
                    mma_f16(acc[mi][ni], a[mi], b[ni]);
        }
    }

#pragma unroll
    for (int mi = 0; mi < 4; mi++) {
        const int gr0 = by * 128 + wm + mi * 16 + l4;
        const int gr1 = gr0 + 8;
#pragma unroll
        for (int ni = 0; ni < 8; ni++) {
            const int gc = bx * 128 + wn + ni * 8 + 2 * lq;
            *(__half2*)(C + (size_t)gr0 * ldc + gc) = __floats2half2_rn(acc[mi][ni][0], acc[mi][ni][1]);
            *(__half2*)(C + (size_t)gr1 * ldc + gc) = __floats2half2_rn(acc[mi][ni][2], acc[mi][ni][3]);
        }
    }
}

// ---------------------------------------------------------------------------
// QK^T with fused block-softmax epilogue. Causal: skip bx>by, mask diag.
// Writes Phat = exp(s - m_b) (half), Mb, Lb per (row, 128-col block bx).
// ---------------------------------------------------------------------------
__global__ void __launch_bounds__(128, 2)
gemm_qk(const __half* __restrict__ A, const __half* __restrict__ B,
        __half* __restrict__ P, float* __restrict__ Mb, float* __restrict__ Lb)
{
    const int bx = blockIdx.x, by = blockIdx.y;
    if (bx > by) return;
    const int lda = DIM, ldb = DIM;
    const int NT = DIM >> 5;

    extern __shared__ __half smem[];
    const uint32_t sbase = smem_u32(smem);
    const int tid = threadIdx.x, wid = tid >> 5, lane = tid & 31;
    const int l4 = lane >> 2, lq = lane & 3;
    const int wm = (wid >> 1) * 64, wn = (wid & 1) * 64;
    const int lt = lane >> 3, lr = lane & 7;
    const uint32_t a_off = (uint32_t)((wm + (lt & 1) * 8 + lr) * 80 + (lt >> 1) * 16);
    const uint32_t b_off = (uint32_t)((wn + (lt >> 1) * 8 + lr) * 80 + (lt & 1) * 16);

    const __half* Ag = A + (size_t)by * 128 * lda;
    const __half* Bg = B + (size_t)bx * 128 * ldb;

    float acc[4][8][4];
#pragma unroll
    for (int i = 0; i < 4; i++)
#pragma unroll
        for (int j = 0; j < 8; j++)
#pragma unroll
            for (int e = 0; e < 4; e++) acc[i][j][e] = 0.f;

    PRODUCE(0); PRODUCE(1); PRODUCE(2);
    for (int i = 0; i < NT; i++) {
        asm volatile("cp.async.wait_group 2;" ::: "memory");
        __syncthreads();
        if (i + 3 < NT) PRODUCE(i + 3);
        else asm volatile("cp.async.commit_group;" ::: "memory");

        const uint32_t stA = sbase + (i & 3) * STAGE_B;
        const uint32_t stB = stA + BOFF;
#pragma unroll
        for (int ks = 0; ks < 2; ks++) {
            const uint32_t kbyte = (uint32_t)(ks * 32);
            uint32_t a[4][4], b[8][2];
#pragma unroll
            for (int mi = 0; mi < 4; mi++)
                ldsm4(a[mi], stA + a_off + (uint32_t)(mi * 16 * 80) + kbyte);
#pragma unroll
            for (int np = 0; np < 4; np++) {
                uint32_t rb[4];
                ldsm4(rb, stB + b_off + (uint32_t)(np * 16 * 80) + kbyte);
                b[np*2][0] = rb[0]; b[np*2][1] = rb[1];
                b[np*2+1][0] = rb[2]; b[np*2+1][1] = rb[3];
            }
#pragma unroll
            for (int mi = 0; mi < 4; mi++)
#pragma unroll
                for (int ni = 0; ni < 8; ni++)
                    mma_f16(acc[mi][ni], a[mi], b[ni]);
        }
    }

    // ---- fused block-softmax epilogue ----
    __syncthreads();                      // pipeline smem now reusable
    float* smax = (float*)smem;           // [2][128]
    float* ssum = smax + 256;             // [2][128]

    // scale + causal mask, per-lane row maxima
    float m0[4], m1[4];
#pragma unroll
    for (int mi = 0; mi < 4; mi++) {
        const int r0 = wm + mi * 16 + l4;      // local rows
        const int r1 = r0 + 8;
        float a0 = -3.4e38f, a1 = -3.4e38f;
#pragma unroll
        for (int ni = 0; ni < 8; ni++) {
            const int c = wn + ni * 8 + 2 * lq;
            float v0 = acc[mi][ni][0] * 0.03125f;
            float v1 = acc[mi][ni][1] * 0.03125f;
            float v2 = acc[mi][ni][2] * 0.03125f;
            float v3 = acc[mi][ni][3] * 0.03125f;
            if (bx == by) {
                if (c     > r0) v0 = -1e30f;
                if (c + 1 > r0) v1 = -1e30f;
                if (c     > r1) v2 = -1e30f;
                if (c + 1 > r1) v3 = -1e30f;
            }
            acc[mi][ni][0] = v0; acc[mi][ni][1] = v1;
            acc[mi][ni][2] = v2; acc[mi][ni][3] = v3;
            a0 = fmaxf(a0, fmaxf(v0, v1));
            a1 = fmaxf(a1, fmaxf(v2, v3));
        }
        m0[mi] = a0; m1[mi] = a1;
    }
#pragma unroll
    for (int mi = 0; mi < 4; mi++) {
        m0[mi] = fmaxf(m0[mi], __shfl_xor_sync(0xffffffffu, m0[mi], 1));
        m0[mi] = fmaxf(m0[mi], __shfl_xor_sync(0xffffffffu, m0[mi], 2));
        m1[mi] = fmaxf(m1[mi], __shfl_xor_sync(0xffffffffu, m1[mi], 1));
        m1[mi] = fmaxf(m1[mi], __shfl_xor_sync(0xffffffffu, m1[mi], 2));
    }
    if (lq == 0) {
#pragma unroll
        for (int mi = 0; mi < 4; mi++) {
            const int r = wm + mi * 16 + l4;
            smax[(wid & 1) * 128 + r]     = m0[mi];
            smax[(wid & 1) * 128 + r + 8] = m1[mi];
        }
    }
    __syncthreads();
    float cm0[4], cm1[4];
#pragma unroll
    for (int mi = 0; mi < 4; mi++) {
        const int r = wm + mi * 16 + l4;
        cm0[mi] = fmaxf(smax[r],     smax[128 + r]);
        cm1[mi] = fmaxf(smax[r + 8], smax[128 + r + 8]);
    }

    // exp + store Phat + row sums
    float s0[4], s1[4];
#pragma unroll
    for (int mi = 0; mi < 4; mi++) {
        const size_t gr0 = (size_t)(by * 128 + wm + mi * 16 + l4);
        const size_t gr1 = gr0 + 8;
        float t0 = 0.f, t1 = 0.f;
#pragma unroll
        for (int ni = 0; ni < 8; ni++) {
            const int gc = bx * 128 + wn + ni * 8 + 2 * lq;
            float e0 = __expf(acc[mi][ni][0] - cm0[mi]);
            float e1 = __expf(acc[mi][ni][1] - cm0[mi]);
            float e2 = __expf(acc[mi][ni][2] - cm1[mi]);
            float e3 = __expf(acc[mi][ni][3] - cm1[mi]);
            t0 += e0 + e1; t1 += e2 + e3;
            *(__half2*)(P + gr0 * SEQ + gc) = __floats2half2_rn(e0, e1);
            *(__half2*)(P + gr1 * SEQ + gc) = __floats2half2_rn(e2, e3);
        }
        s0[mi] = t0; s1[mi] = t1;
    }
#pragma unroll
    for (int mi = 0; mi < 4; mi++) {
        s0[mi] += __shfl_xor_sync(0xffffffffu, s0[mi], 1);
        s0[mi] += __shfl_xor_sync(0xffffffffu, s0[mi], 2);
        s1[mi] += __shfl_xor_sync(0xffffffffu, s1[mi], 1);
        s1[mi] += __shfl_xor_sync(0xffffffffu, s1[mi], 2);
    }
    if (lq == 0) {
#pragma unroll
        for (int mi = 0; mi < 4; mi++) {
            const int r = wm + mi * 16 + l4;
            ssum[(wid & 1) * 128 + r]     = s0[mi];
            ssum[(wid & 1) * 128 + r + 8] = s1[mi];
        }
    }
    __syncthreads();
    if ((wid & 1) == 0 && lq == 0) {
#pragma unroll
        for (int mi = 0; mi < 4; mi++) {
            const int r = wm + mi * 16 + l4;
            const size_t g0 = (size_t)(by * 128 + r) * 64 + bx;
            const size_t g1 = (size_t)(by * 128 + r + 8) * 64 + bx;
            Mb[g0] = cm0[mi]; Lb[g0] = ssum[r] + ssum[128 + r];
            Mb[g1] = cm1[mi]; Lb[g1] = ssum[r + 8] + ssum[128 + r + 8];
        }
    }
}

// ---------------------------------------------------------------------------
// Per-row stats: combine (m_b, l_b) over nb blocks -> scale_b = e^{mb-m}/L.
// One warp per row.
// ---------------------------------------------------------------------------
__global__ void __launch_bounds__(256)
stats_k(const float* __restrict__ Mb, const float* __restrict__ Lb,
        __half* __restrict__ SC)
{
    const int row  = blockIdx.x * 8 + (threadIdx.x >> 5);
    const int lane = threadIdx.x & 31;
    const int nb   = (row >> 7) + 1;
    const size_t base = (size_t)row * 64;

    float mA = (lane      < nb) ? Mb[base + lane]      : -3.4e38f;
    float mB = (lane + 32 < nb) ? Mb[base + lane + 32] : -3.4e38f;
    float mm = fmaxf(mA, mB);
#pragma unroll
    for (int s = 16; s > 0; s >>= 1)
        mm = fmaxf(mm, __shfl_xor_sync(0xffffffffu, mm, s));

    float eA = (lane      < nb) ? __expf(mA - mm) : 0.f;
    float eB = (lane + 32 < nb) ? __expf(mB - mm) : 0.f;
    float part = (lane < nb ? Lb[base + lane] * eA : 0.f)
               + (lane + 32 < nb ? Lb[base + lane + 32] * eB : 0.f);
#pragma unroll
    for (int s = 16; s > 0; s >>= 1)
        part += __shfl_xor_sync(0xffffffffu, part, s);
    const float inv = 1.f / part;

    if (lane < nb)      SC[base + lane]      = __float2half(eA * inv);
    if (lane + 32 < nb) SC[base + lane + 32] = __float2half(eB * inv);
}

// ---------------------------------------------------------------------------
// PV: out = (Phat * scale) @ Vt^T, fp32 out. K truncated to (by+1)*128.
// by REVERSED (longest CTAs launch first). A fragments scaled in-register
// by per-(row, 128-k-block) half scale, double-buffered prefetch.
// ---------------------------------------------------------------------------
__global__ void __launch_bounds__(128, 2)
gemm_pv(const __half* __restrict__ Phat, const __half* __restrict__ Vt,
        const __half* __restrict__ SC, float* __restrict__ C)
{
    const int bx = blockIdx.x;
    const int by = (int)gridDim.y - 1 - (int)blockIdx.y;   // longest-first
    const int lda = SEQ, ldb = SEQ, ldc = DIM;
    const int K  = (by + 1) * 128;
    const int NT = K >> 5;

    extern __shared__ __half smem[];
    const uint32_t sbase = smem_u32(smem);
    const int tid = threadIdx.x, wid = tid >> 5, lane = tid & 31;
    const int l4 = lane >> 2, lq = lane & 3;
    const int wm = (wid >> 1) * 64, wn = (wid & 1) * 64;
    const int lt = lane >> 3, lr = lane & 7;
    const uint32_t a_off = (uint32_t)((wm + (lt & 1) * 8 + lr) * 80 + (lt >> 1) * 16);
    const uint32_t b_off = (uint32_t)((wn + (lt >> 1) * 8 + lr) * 80 + (lt & 1) * 16);

    const __half* Ag = Phat + (size_t)by * 128 * lda;
    const __half* Bg = Vt + (size_t)bx * 128 * ldb;
    const size_t scbase = (size_t)(by * 128) * 64;

    float acc[4][8][4];
#pragma unroll
    for (int i = 0; i < 4; i++)
#pragma unroll
        for (int j = 0; j < 8; j++)
#pragma unroll
            for (int e = 0; e < 4; e++) acc[i][j][e] = 0.f;

    // double-buffered row-block scales: sc[buf][mi][h]
    __half2 scb[2][4][2];
#define LOADSC(b, buf) do {                                                   \
        _Pragma("unroll")                                                     \
        for (int _mi = 0; _mi < 4; _mi++) {                                   \
            const __half* _p = SC + scbase + (size_t)(wm + _mi * 16 + l4) * 64 + (b); \
            scb[buf][_mi][0] = __half2half2(_p[0]);                           \
            scb[buf][_mi][1] = __half2half2(_p[8 * 64]);                      \
        }                                                                     \
    } while (0)

    LOADSC(0, 0);

    PRODUCE(0); PRODUCE(1); PRODUCE(2);
    for (int i = 0; i < NT; i++) {
        asm volatile("cp.async.wait_group 2;" ::: "memory");
        __syncthreads();
        if (i + 3 < NT) PRODUCE(i + 3);
        else asm volatile("cp.async.commit_group;" ::: "memory");

        // prefetch next block's scales one tile ahead
        if ((i & 3) == 1 && (i >> 2) + 1 <= by) LOADSC((i >> 2) + 1, ((i >> 2) + 1) & 1);
        const int sbuf = (i >> 2) & 1;

        const uint32_t stA = sbase + (i & 3) * STAGE_B;
        const uint32_t stB = stA + BOFF;
#pragma unroll
        for (int ks = 0; ks < 2; ks++) {
            const uint32_t kbyte = (uint32_t)(ks * 32);
            uint32_t a[4][4], b[8][2];
#pragma unroll
            for (int mi = 0; mi < 4; mi++) {
                ldsm4(a[mi], stA + a_off + (uint32_t)(mi * 16 * 80) + kbyte);
                a[mi][0] = hmul2_u(a[mi][0], scb[sbuf][mi][0]);
                a[mi][2] = hmul2_u(a[mi][2], scb[sbuf][mi][0]);
                a[mi][1] = hmul2_u(a[mi][1], scb[sbuf][mi][1]);
                a[mi][3] = hmul2_u(a[mi][3], scb[sbuf][mi][1]);
            }
#pragma unroll
            for (int np = 0; np < 4; np++) {
                uint32_t rb[4];
                ldsm4(rb, stB + b_off + (uint32_t)(np * 16 * 80) + kbyte);
                b[np*2][0] = rb[0]; b[np*2][1] = rb[1];
                b[np*2+1][0] = rb[2]; b[np*2+1][1] = rb[3];
            }
#pragma unroll
            for (int mi = 0; mi < 4; mi++)
#pragma unroll
                for (int ni = 0; ni < 8; ni++)
                    mma_f16(acc[mi][ni], a[mi], b[ni]);
        }
    }
#undef LOADSC

#pragma unroll
    for (int mi = 0; mi < 4; mi++) {
        const int gr0 = by * 128 + wm + mi * 16 + l4;
        const int gr1 = gr0 + 8;
#pragma unroll
        for (int ni = 0; ni < 8; ni++) {
            const int gc = bx * 128 + wn + ni * 8 + 2 * lq;
            *(float2*)(C + (size_t)gr0 * ldc + gc) = make_float2(acc[mi][ni][0], acc[mi][ni][1]);
            *(float2*)(C + (size_t)gr1 * ldc + gc) = make_float2(acc[mi][ni][2], acc[mi][ni][3]);
        }
    }
}

// ---------------------------------------------------------------------------
__global__ void __launch_bounds__(256)
conv_all(const float* __restrict__ x,  const float* __restrict__ wq,
         const float* __restrict__ wk, const float* __restrict__ wv,
         __half* __restrict__ hX,  __half* __restrict__ hWq,
         __half* __restrict__ hWk, __half* __restrict__ hWv)
{
    const long long NX = (long long)SEQ * DIM / 4;
    const long long NW = (long long)DIM * DIM / 4;
    long long f4 = (long long)blockIdx.x * 256 + threadIdx.x;
    const float* s; __half* d; long long off;
    if      (f4 < NX)          { s = x;  d = hX;  off = f4; }
    else if (f4 < NX + NW)     { s = wq; d = hWq; off = f4 - NX; }
    else if (f4 < NX + 2 * NW) { s = wk; d = hWk; off = f4 - NX - NW; }
    else                       { s = wv; d = hWv; off = f4 - NX - 2 * NW; }
    float4 v = *(const float4*)(s + off * 4);
    *(__half2*)(d + off * 4)     = __floats2half2_rn(v.x, v.y);
    *(__half2*)(d + off * 4 + 2) = __floats2half2_rn(v.z, v.w);
}

__global__ void __launch_bounds__(256) transpose_h(const __half* __restrict__ src,
                                                   __half* __restrict__ dst)
{
    __shared__ __half t[32][33];
    const int x = blockIdx.x * 32 + threadIdx.x;
    const int y0 = blockIdx.y * 32;
    for (int j = threadIdx.y; j < 32; j += 8)
        t[j][threadIdx.x] = src[(size_t)(y0 + j) * DIM + x];
    __syncthreads();
    const int xo = y0 + threadIdx.x;
    const int yo0 = blockIdx.x * 32;
    for (int j = threadIdx.y; j < 32; j += 8)
        dst[(size_t)(yo0 + j) * SEQ + xo] = t[threadIdx.x][j];
}

// ---------------------------------------------------------------------------
extern "C" void kernel_launch(void* const* d_in, const int* in_sizes, int n_in,
                              void* d_out, int out_size)
{
    const float* x  = (const float*)d_in[0];
    const float* wq = (const float*)d_in[1];
    const float* wk = (const float*)d_in[2];
    const float* wv = (const float*)d_in[3];
    float* out = (float*)d_out;

    __half *hX, *hWq, *hWk, *hWv, *hQ, *hK, *hV, *hVt, *hP, *sc;
    float *Mb, *Lb;
    cudaGetSymbolAddress((void**)&hX,  g_hX);
    cudaGetSymbolAddress((void**)&hWq, g_hWq);
    cudaGetSymbolAddress((void**)&hWk, g_hWk);
    cudaGetSymbolAddress((void**)&hWv, g_hWv);
    cudaGetSymbolAddress((void**)&hQ,  g_hQ);
    cudaGetSymbolAddress((void**)&hK,  g_hK);
    cudaGetSymbolAddress((void**)&hV,  g_hV);
    cudaGetSymbolAddress((void**)&hVt, g_hVt);
    cudaGetSymbolAddress((void**)&hP,  g_hP);
    cudaGetSymbolAddress((void**)&sc,  g_sc);
    cudaGetSymbolAddress((void**)&Mb,  g_Mb);
    cudaGetSymbolAddress((void**)&Lb,  g_Lb);

    const int SMEM_DYN = 4 * STAGE_B;            // 81920 bytes
    cudaFuncSetAttribute(gemm_h,  cudaFuncAttributeMaxDynamicSharedMemorySize, SMEM_DYN);
    cudaFuncSetAttribute(gemm_qk, cudaFuncAttributeMaxDynamicSharedMemorySize, SMEM_DYN);
    cudaFuncSetAttribute(gemm_pv, cudaFuncAttributeMaxDynamicSharedMemorySize, SMEM_DYN);

    const long long NCONV = (long long)SEQ * DIM / 4 + 3LL * DIM * DIM / 4;
    conv_all<<<(unsigned)((NCONV + 255) / 256), 256>>>(x, wq, wk, wv, hX, hWq, hWk, hWv);

    dim3 gthr(128);
    dim3 gproj(DIM / 128, SEQ / 128);   // (8, 64)
    dim3 gsc(SEQ / 128, SEQ / 128);     // (64, 64)

    gemm_h<<<gproj, gthr, SMEM_DYN>>>(hX, hWq, hQ, DIM, DIM, DIM, DIM);
    gemm_h<<<gproj, gthr, SMEM_DYN>>>(hX, hWk, hK, DIM, DIM, DIM, DIM);
    gemm_h<<<gproj, gthr, SMEM_DYN>>>(hX, hWv, hV, DIM, DIM, DIM, DIM);

    transpose_h<<<dim3(DIM / 32, SEQ / 32), dim3(32, 8)>>>(hV, hVt);

    gemm_qk<<<gsc, gthr, SMEM_DYN>>>(hQ, hK, hP, Mb, Lb);

    stats_k<<<SEQ / 8, 256>>>(Mb, Lb, sc);

    gemm_pv<<<gproj, gthr, SMEM_DYN>>>(hP, hVt, sc, out);
}

// round 12
// speedup vs baseline: 7.4861x; 1.0629x over previous
#include <cuda_runtime.h>
#include <cuda_fp16.h>
#include <math.h>
#include <stdint.h>

#define SEQ 8192
#define DIM 1024

// ---- scratch (__device__ globals; no allocs allowed) ----
__device__ __half g_hX [SEQ * DIM];
__device__ __half g_hWq[DIM * DIM];
__device__ __half g_hWk[DIM * DIM];
__device__ __half g_hWv[DIM * DIM];
__device__ __half g_hQ [SEQ * DIM];
__device__ __half g_hK [SEQ * DIM];
__device__ __half g_hVt[DIM * SEQ];            // V^T (K-major B for PV)
__device__ __half g_hP [(size_t)SEQ * SEQ];    // unscaled exp(s - m_b), half
__device__ float  g_Mb [(size_t)SEQ * 64];     // per (row, block) max
__device__ float  g_Lb [(size_t)SEQ * 64];     // per (row, block) sum
__device__ __half g_sc [(size_t)SEQ * 64];     // per (row, block) scale e^{mb-m}/L

// ---------------------------------------------------------------------------
__device__ __forceinline__ uint32_t smem_u32(const void* p) {
    uint32_t a;
    asm("{ .reg .u64 t; cvta.to.shared.u64 t, %1; cvt.u32.u64 %0, t; }" : "=r"(a) : "l"(p));
    return a;
}
__device__ __forceinline__ void mma_f16(float* c, const uint32_t* a, const uint32_t* b) {
    asm volatile(
        "mma.sync.aligned.m16n8k16.row.col.f32.f16.f16.f32 "
        "{%0,%1,%2,%3}, {%4,%5,%6,%7}, {%8,%9}, {%0,%1,%2,%3};\n"
        : "+f"(c[0]), "+f"(c[1]), "+f"(c[2]), "+f"(c[3])
        : "r"(a[0]), "r"(a[1]), "r"(a[2]), "r"(a[3]), "r"(b[0]), "r"(b[1]));
}
__device__ __forceinline__ void ldsm4(uint32_t* r, uint32_t addr) {
    asm volatile("ldmatrix.sync.aligned.m8n8.x4.shared.b16 {%0,%1,%2,%3}, [%4];"
                 : "=r"(r[0]), "=r"(r[1]), "=r"(r[2]), "=r"(r[3]) : "r"(addr));
}
__device__ __forceinline__ uint32_t hmul2_u(uint32_t a, __half2 s) {
    __half2 v = *(__half2*)&a;
    v = __hmul2(v, s);
    return *(uint32_t*)&v;
}
#define CP16(dst, src) \
    asm volatile("cp.async.cg.shared.global [%0], [%1], 16;" :: "r"(dst), "l"(src) : "memory")

#define STAGE_B (2 * 128 * 40 * 2)   // 20480 bytes per stage
#define BOFF    (128 * 40 * 2)

#define PRODUCE(t) do {                                                       \
        const __half* _Ab = Ag + (t) * 32;                                    \
        const __half* _Bb = Bg + (t) * 32;                                    \
        const uint32_t _sA = sbase + ((t) & 3) * STAGE_B;                     \
        const uint32_t _sB = _sA + BOFF;                                      \
        _Pragma("unroll")                                                     \
        for (int _j = 0; _j < 4; _j++) {                                      \
            int _q = _j * 128 + tid;                                          \
            int _r = _q >> 2, _c = _q & 3;                                    \
            uint32_t _so = _r * 80 + _c * 16;                                 \
            CP16(_sA + _so, _Ab + (size_t)_r * lda + _c * 8);                 \
            CP16(_sB + _so, _Bb + (size_t)_r * ldb + _c * 8);                 \
        }                                                                     \
        asm volatile("cp.async.commit_group;" ::: "memory");                  \
    } while (0)

// mainloop (consumes NT 32-K tiles into acc[4][8][4]); one sync per tile
#define MAINLOOP()                                                            \
    PRODUCE(0); PRODUCE(1); PRODUCE(2);                                       \
    for (int i = 0; i < NT; i++) {                                            \
        asm volatile("cp.async.wait_group 2;" ::: "memory");                  \
        __syncthreads();                                                      \
        if (i + 3 < NT) PRODUCE(i + 3);                                       \
        else asm volatile("cp.async.commit_group;" ::: "memory");             \
        const uint32_t stA = sbase + (i & 3) * STAGE_B;                       \
        const uint32_t stB = stA + BOFF;                                      \
        _Pragma("unroll")                                                     \
        for (int ks = 0; ks < 2; ks++) {                                      \
            const uint32_t kbyte = (uint32_t)(ks * 32);                       \
            uint32_t a[4][4], b[8][2];                                        \
            _Pragma("unroll")                                                 \
            for (int mi = 0; mi < 4; mi++)                                    \
                ldsm4(a[mi], stA + a_off + (uint32_t)(mi * 16 * 80) + kbyte); \
            _Pragma("unroll")                                                 \
            for (int np = 0; np < 4; np++) {                                  \
                uint32_t rb[4];                                               \
                ldsm4(rb, stB + b_off + (uint32_t)(np * 16 * 80) + kbyte);    \
                b[np*2][0] = rb[0]; b[np*2][1] = rb[1];                       \
                b[np*2+1][0] = rb[2]; b[np*2+1][1] = rb[3];                   \
            }                                                                 \
            _Pragma("unroll")                                                 \
            for (int mi = 0; mi < 4; mi++)                                    \
                _Pragma("unroll")                                             \
                for (int ni = 0; ni < 8; ni++)                                \
                    mma_f16(acc[mi][ni], a[mi], b[ni]);                       \
        }                                                                     \
    }

#define DECL_COMMON()                                                         \
    extern __shared__ __half smem[];                                          \
    const uint32_t sbase = smem_u32(smem);                                    \
    const int tid = threadIdx.x, wid = tid >> 5, lane = tid & 31;             \
    const int l4 = lane >> 2, lq = lane & 3;                                  \
    const int wm = (wid >> 1) * 64, wn = (wid & 1) * 64;                      \
    const int lt = lane >> 3, lr = lane & 7;                                  \
    const uint32_t a_off = (uint32_t)((wm + (lt & 1) * 8 + lr) * 80 + (lt >> 1) * 16); \
    const uint32_t b_off = (uint32_t)((wn + (lt >> 1) * 8 + lr) * 80 + (lt & 1) * 16); \
    float acc[4][8][4];                                                       \
    _Pragma("unroll")                                                         \
    for (int i = 0; i < 4; i++)                                               \
        _Pragma("unroll")                                                     \
        for (int j = 0; j < 8; j++)                                           \
            _Pragma("unroll")                                                 \
            for (int e = 0; e < 4; e++) acc[i][j][e] = 0.f;

// ---------------------------------------------------------------------------
// Fused QKV projection: grid (24, 64). bx/8 selects {Q, K, V}.
// Q,K: write half rows. V: transpose tile through smem, write Vt directly.
// ---------------------------------------------------------------------------
__global__ void __launch_bounds__(128, 2)
gemm_qkv(const __half* __restrict__ X,
         const __half* __restrict__ Wq, const __half* __restrict__ Wk,
         const __half* __restrict__ Wv,
         __half* __restrict__ Q, __half* __restrict__ Kh, __half* __restrict__ Vt)
{
    const int bxs = blockIdx.x;          // 0..23
    const int sel = bxs >> 3;            // 0=Q 1=K 2=V
    const int bx  = bxs & 7;
    const int by  = blockIdx.y;
    const int lda = DIM, ldb = DIM;
    const int NT  = DIM >> 5;

    DECL_COMMON();
    const __half* Ag = X + (size_t)by * 128 * lda;
    const __half* W  = (sel == 0) ? Wq : (sel == 1) ? Wk : Wv;
    const __half* Bg = W + (size_t)bx * 128 * ldb;

    MAINLOOP();

    if (sel < 2) {
        __half* C = (sel == 0) ? Q : Kh;
#pragma unroll
        for (int mi = 0; mi < 4; mi++) {
            const int gr0 = by * 128 + wm + mi * 16 + l4;
            const int gr1 = gr0 + 8;
#pragma unroll
            for (int ni = 0; ni < 8; ni++) {
                const int gc = bx * 128 + wn + ni * 8 + 2 * lq;
                *(__half2*)(C + (size_t)gr0 * DIM + gc) = __floats2half2_rn(acc[mi][ni][0], acc[mi][ni][1]);
                *(__half2*)(C + (size_t)gr1 * DIM + gc) = __floats2half2_rn(acc[mi][ni][2], acc[mi][ni][3]);
            }
        }
    } else {
        // V: transpose through smem -> Vt[dim][seq]
        __syncthreads();                         // last consume done; reuse smem
        __half* sT = smem;                       // [128][136] halves (34816 B)
#pragma unroll
        for (int mi = 0; mi < 4; mi++) {
            const int r0 = wm + mi * 16 + l4;    // local seq rows
            const int r1 = r0 + 8;
#pragma unroll
            for (int ni = 0; ni < 8; ni++) {
                const int c = wn + ni * 8 + 2 * lq;   // local dim cols
                sT[(size_t)c * 136 + r0]       = __float2half_rn(acc[mi][ni][0]);
                sT[(size_t)(c + 1) * 136 + r0] = __float2half_rn(acc[mi][ni][1]);
                sT[(size_t)c * 136 + r1]       = __float2half_rn(acc[mi][ni][2]);
                sT[(size_t)(c + 1) * 136 + r1] = __float2half_rn(acc[mi][ni][3]);
            }
        }
        __syncthreads();
        // thread tid owns dim-row d = tid: 128 contiguous halves -> Vt
        const int d = tid;
        __half* dst = Vt + (size_t)(bx * 128 + d) * SEQ + (size_t)by * 128;
        const __half* src = sT + (size_t)d * 136;
#pragma unroll
        for (int j = 0; j < 16; j++)
            *(float4*)(dst + j * 8) = *(const float4*)(src + j * 8);
    }
}

// ---------------------------------------------------------------------------
// QK^T with fused block-softmax epilogue (R11-proven).
// ---------------------------------------------------------------------------
__global__ void __launch_bounds__(128, 2)
gemm_qk(const __half* __restrict__ A, const __half* __restrict__ B,
        __half* __restrict__ P, float* __restrict__ Mb, float* __restrict__ Lb)
{
    const int bx = blockIdx.x, by = blockIdx.y;
    if (bx > by) return;
    const int lda = DIM, ldb = DIM;
    const int NT = DIM >> 5;

    DECL_COMMON();
    const __half* Ag = A + (size_t)by * 128 * lda;
    const __half* Bg = B + (size_t)bx * 128 * ldb;

    MAINLOOP();

    __syncthreads();
    float* smax = (float*)smem;
    float* ssum = smax + 256;

    float m0[4], m1[4];
#pragma unroll
    for (int mi = 0; mi < 4; mi++) {
        const int r0 = wm + mi * 16 + l4;
        const int r1 = r0 + 8;
        float a0 = -3.4e38f, a1 = -3.4e38f;
#pragma unroll
        for (int ni = 0; ni < 8; ni++) {
            const int c = wn + ni * 8 + 2 * lq;
            float v0 = acc[mi][ni][0] * 0.03125f;
            float v1 = acc[mi][ni][1] * 0.03125f;
            float v2 = acc[mi][ni][2] * 0.03125f;
            float v3 = acc[mi][ni][3] * 0.03125f;
            if (bx == by) {
                if (c     > r0) v0 = -1e30f;
                if (c + 1 > r0) v1 = -1e30f;
                if (c     > r1) v2 = -1e30f;
                if (c + 1 > r1) v3 = -1e30f;
            }
            acc[mi][ni][0] = v0; acc[mi][ni][1] = v1;
            acc[mi][ni][2] = v2; acc[mi][ni][3] = v3;
            a0 = fmaxf(a0, fmaxf(v0, v1));
            a1 = fmaxf(a1, fmaxf(v2, v3));
        }
        m0[mi] = a0; m1[mi] = a1;
    }
#pragma unroll
    for (int mi = 0; mi < 4; mi++) {
        m0[mi] = fmaxf(m0[mi], __shfl_xor_sync(0xffffffffu, m0[mi], 1));
        m0[mi] = fmaxf(m0[mi], __shfl_xor_sync(0xffffffffu, m0[mi], 2));
        m1[mi] = fmaxf(m1[mi], __shfl_xor_sync(0xffffffffu, m1[mi], 1));
        m1[mi] = fmaxf(m1[mi], __shfl_xor_sync(0xffffffffu, m1[mi], 2));
    }
    if (lq == 0) {
#pragma unroll
        for (int mi = 0; mi < 4; mi++) {
            const int r = wm + mi * 16 + l4;
            smax[(wid & 1) * 128 + r]     = m0[mi];
            smax[(wid & 1) * 128 + r + 8] = m1[mi];
        }
    }
    __syncthreads();
    float cm0[4], cm1[4];
#pragma unroll
    for (int mi = 0; mi < 4; mi++) {
        const int r = wm + mi * 16 + l4;
        cm0[mi] = fmaxf(smax[r],     smax[128 + r]);
        cm1[mi] = fmaxf(smax[r + 8], smax[128 + r + 8]);
    }

    float s0[4], s1[4];
#pragma unroll
    for (int mi = 0; mi < 4; mi++) {
        const size_t gr0 = (size_t)(by * 128 + wm + mi * 16 + l4);
        const size_t gr1 = gr0 + 8;
        float t0 = 0.f, t1 = 0.f;
#pragma unroll
        for (int ni = 0; ni < 8; ni++) {
            const int gc = bx * 128 + wn + ni * 8 + 2 * lq;
            float e0 = __expf(acc[mi][ni][0] - cm0[mi]);
            float e1 = __expf(acc[mi][ni][1] - cm0[mi]);
            float e2 = __expf(acc[mi][ni][2] - cm1[mi]);
            float e3 = __expf(acc[mi][ni][3] - cm1[mi]);
            t0 += e0 + e1; t1 += e2 + e3;
            *(__half2*)(P + gr0 * SEQ + gc) = __floats2half2_rn(e0, e1);
            *(__half2*)(P + gr1 * SEQ + gc) = __floats2half2_rn(e2, e3);
        }
        s0[mi] = t0; s1[mi] = t1;
    }
#pragma unroll
    for (int mi = 0; mi < 4; mi++) {
        s0[mi] += __shfl_xor_sync(0xffffffffu, s0[mi], 1);
        s0[mi] += __shfl_xor_sync(0xffffffffu, s0[mi], 2);
        s1[mi] += __shfl_xor_sync(0xffffffffu, s1[mi], 1);
        s1[mi] += __shfl_xor_sync(0xffffffffu, s1[mi], 2);
    }
    if (lq == 0) {
#pragma unroll
        for (int mi = 0; mi < 4; mi++) {
            const int r = wm + mi * 16 + l4;
            ssum[(wid & 1) * 128 + r]     = s0[mi];
            ssum[(wid & 1) * 128 + r + 8] = s1[mi];
        }
    }
    __syncthreads();
    if ((wid & 1) == 0 && lq == 0) {
#pragma unroll
        for (int mi = 0; mi < 4; mi++) {
            const int r = wm + mi * 16 + l4;
            const size_t g0 = (size_t)(by * 128 + r) * 64 + bx;
            const size_t g1 = (size_t)(by * 128 + r + 8) * 64 + bx;
            Mb[g0] = cm0[mi]; Lb[g0] = ssum[r] + ssum[128 + r];
            Mb[g1] = cm1[mi]; Lb[g1] = ssum[r + 8] + ssum[128 + r + 8];
        }
    }
}

// ---------------------------------------------------------------------------
__global__ void __launch_bounds__(256)
stats_k(const float* __restrict__ Mb, const float* __restrict__ Lb,
        __half* __restrict__ SC)
{
    const int row  = blockIdx.x * 8 + (threadIdx.x >> 5);
    const int lane = threadIdx.x & 31;
    const int nb   = (row >> 7) + 1;
    const size_t base = (size_t)row * 64;

    float mA = (lane      < nb) ? Mb[base + lane]      : -3.4e38f;
    float mB = (lane + 32 < nb) ? Mb[base + lane + 32] : -3.4e38f;
    float mm = fmaxf(mA, mB);
#pragma unroll
    for (int s = 16; s > 0; s >>= 1)
        mm = fmaxf(mm, __shfl_xor_sync(0xffffffffu, mm, s));

    float eA = (lane      < nb) ? __expf(mA - mm) : 0.f;
    float eB = (lane + 32 < nb) ? __expf(mB - mm) : 0.f;
    float part = (lane < nb ? Lb[base + lane] * eA : 0.f)
               + (lane + 32 < nb ? Lb[base + lane + 32] * eB : 0.f);
#pragma unroll
    for (int s = 16; s > 0; s >>= 1)
        part += __shfl_xor_sync(0xffffffffu, part, s);
    const float inv = 1.f / part;

    if (lane < nb)      SC[base + lane]      = __float2half(eA * inv);
    if (lane + 32 < nb) SC[base + lane + 32] = __float2half(eB * inv);
}

// ---------------------------------------------------------------------------
// PV (R11-proven): out = (Phat * scale) @ Vt^T, longest-first, fp32 out.
// ---------------------------------------------------------------------------
__global__ void __launch_bounds__(128, 2)
gemm_pv(const __half* __restrict__ Phat, const __half* __restrict__ Vt,
        const __half* __restrict__ SC, float* __restrict__ C)
{
    const int bx = blockIdx.x;
    const int by = (int)gridDim.y - 1 - (int)blockIdx.y;
    const int lda = SEQ, ldb = SEQ;
    const int NT = (by + 1) * 4;

    DECL_COMMON();
    const __half* Ag = Phat + (size_t)by * 128 * lda;
    const __half* Bg = Vt + (size_t)bx * 128 * ldb;
    const size_t scbase = (size_t)(by * 128) * 64;

    __half2 scb[2][4][2];
#define LOADSC(b, buf) do {                                                   \
        _Pragma("unroll")                                                     \
        for (int _mi = 0; _mi < 4; _mi++) {                                   \
            const __half* _p = SC + scbase + (size_t)(wm + _mi * 16 + l4) * 64 + (b); \
            scb[buf][_mi][0] = __half2half2(_p[0]);                           \
            scb[buf][_mi][1] = __half2half2(_p[8 * 64]);                      \
        }                                                                     \
    } while (0)

    LOADSC(0, 0);

    PRODUCE(0); PRODUCE(1); PRODUCE(2);
    for (int i = 0; i < NT; i++) {
        asm volatile("cp.async.wait_group 2;" ::: "memory");
        __syncthreads();
        if (i + 3 < NT) PRODUCE(i + 3);
        else asm volatile("cp.async.commit_group;" ::: "memory");

        if ((i & 3) == 1 && (i >> 2) + 1 <= by) LOADSC((i >> 2) + 1, ((i >> 2) + 1) & 1);
        const int sbuf = (i >> 2) & 1;

        const uint32_t stA = sbase + (i & 3) * STAGE_B;
        const uint32_t stB = stA + BOFF;
#pragma unroll
        for (int ks = 0; ks < 2; ks++) {
            const uint32_t kbyte = (uint32_t)(ks * 32);
            uint32_t a[4][4], b[8][2];
#pragma unroll
            for (int mi = 0; mi < 4; mi++) {
                ldsm4(a[mi], stA + a_off + (uint32_t)(mi * 16 * 80) + kbyte);
                a[mi][0] = hmul2_u(a[mi][0], scb[sbuf][mi][0]);
                a[mi][2] = hmul2_u(a[mi][2], scb[sbuf][mi][0]);
                a[mi][1] = hmul2_u(a[mi][1], scb[sbuf][mi][1]);
                a[mi][3] = hmul2_u(a[mi][3], scb[sbuf][mi][1]);
            }
#pragma unroll
            for (int np = 0; np < 4; np++) {
                uint32_t rb[4];
                ldsm4(rb, stB + b_off + (uint32_t)(np * 16 * 80) + kbyte);
                b[np*2][0] = rb[0]; b[np*2][1] = rb[1];
                b[np*2+1][0] = rb[2]; b[np*2+1][1] = rb[3];
            }
#pragma unroll
            for (int mi = 0; mi < 4; mi++)
#pragma unroll
                for (int ni = 0; ni < 8; ni++)
                    mma_f16(acc[mi][ni], a[mi], b[ni]);
        }
    }
#undef LOADSC

#pragma unroll
    for (int mi = 0; mi < 4; mi++) {
        const int gr0 = by * 128 + wm + mi * 16 + l4;
        const int gr1 = gr0 + 8;
#pragma unroll
        for (int ni = 0; ni < 8; ni++) {
            const int gc = bx * 128 + wn + ni * 8 + 2 * lq;
            *(float2*)(C + (size_t)gr0 * DIM + gc) = make_float2(acc[mi][ni][0], acc[mi][ni][1]);
            *(float2*)(C + (size_t)gr1 * DIM + gc) = make_float2(acc[mi][ni][2], acc[mi][ni][3]);
        }
    }
}

// ---------------------------------------------------------------------------
__global__ void __launch_bounds__(256)
conv_all(const float* __restrict__ x,  const float* __restrict__ wq,
         const float* __restrict__ wk, const float* __restrict__ wv,
         __half* __restrict__ hX,  __half* __restrict__ hWq,
         __half* __restrict__ hWk, __half* __restrict__ hWv)
{
    const long long NX = (long long)SEQ * DIM / 4;
    const long long NW = (long long)DIM * DIM / 4;
    long long f4 = (long long)blockIdx.x * 256 + threadIdx.x;
    const float* s; __half* d; long long off;
    if      (f4 < NX)          { s = x;  d = hX;  off = f4; }
    else if (f4 < NX + NW)     { s = wq; d = hWq; off = f4 - NX; }
    else if (f4 < NX + 2 * NW) { s = wk; d = hWk; off = f4 - NX - NW; }
    else                       { s = wv; d = hWv; off = f4 - NX - 2 * NW; }
    float4 v = *(const float4*)(s + off * 4);
    *(__half2*)(d + off * 4)     = __floats2half2_rn(v.x, v.y);
    *(__half2*)(d + off * 4 + 2) = __floats2half2_rn(v.z, v.w);
}

// ---------------------------------------------------------------------------
extern "C" void kernel_launch(void* const* d_in, const int* in_sizes, int n_in,
                              void* d_out, int out_size)
{
    const float* x  = (const float*)d_in[0];
    const float* wq = (const float*)d_in[1];
    const float* wk = (const float*)d_in[2];
    const float* wv = (const float*)d_in[3];
    float* out = (float*)d_out;

    __half *hX, *hWq, *hWk, *hWv, *hQ, *hK, *hVt, *hP, *sc;
    float *Mb, *Lb;
    cudaGetSymbolAddress((void**)&hX,  g_hX);
    cudaGetSymbolAddress((void**)&hWq, g_hWq);
    cudaGetSymbolAddress((void**)&hWk, g_hWk);
    cudaGetSymbolAddress((void**)&hWv, g_hWv);
    cudaGetSymbolAddress((void**)&hQ,  g_hQ);
    cudaGetSymbolAddress((void**)&hK,  g_hK);
    cudaGetSymbolAddress((void**)&hVt, g_hVt);
    cudaGetSymbolAddress((void**)&hP,  g_hP);
    cudaGetSymbolAddress((void**)&sc,  g_sc);
    cudaGetSymbolAddress((void**)&Mb,  g_Mb);
    cudaGetSymbolAddress((void**)&Lb,  g_Lb);

    const int SMEM_DYN = 4 * STAGE_B;            // 81920 bytes
    cudaFuncSetAttribute(gemm_qkv, cudaFuncAttributeMaxDynamicSharedMemorySize, SMEM_DYN);
    cudaFuncSetAttribute(gemm_qk,  cudaFuncAttributeMaxDynamicSharedMemorySize, SMEM_DYN);
    cudaFuncSetAttribute(gemm_pv,  cudaFuncAttributeMaxDynamicSharedMemorySize, SMEM_DYN);

    const long long NCONV = (long long)SEQ * DIM / 4 + 3LL * DIM * DIM / 4;
    conv_all<<<(unsigned)((NCONV + 255) / 256), 256>>>(x, wq, wk, wv, hX, hWq, hWk, hWv);

    dim3 gthr(128);

    // fused Q,K,V projections (V transposed in epilogue)
    gemm_qkv<<<dim3(24, 64), gthr, SMEM_DYN>>>(hX, hWq, hWk, hWv, hQ, hK, hVt);

    // scores + block softmax
    gemm_qk<<<dim3(64, 64), gthr, SMEM_DYN>>>(hQ, hK, hP, Mb, Lb);

    stats_k<<<SEQ / 8, 256>>>(Mb, Lb, sc);

    // out = (Phat * scale) @ V
    gemm_pv<<<dim3(8, 64), gthr, SMEM_DYN>>>(hP, hVt, sc, out);
}

// round 14
// speedup vs baseline: 7.5126x; 1.0035x over previous
#include <cuda_runtime.h>
#include <cuda_fp16.h>
#include <math.h>
#include <stdint.h>

#define SEQ 8192
#define DIM 1024

// ---- scratch (__device__ globals; no allocs allowed) ----
__device__ __half g_hX [SEQ * DIM];
__device__ __half g_hWq[DIM * DIM];
__device__ __half g_hWk[DIM * DIM];
__device__ __half g_hWv[DIM * DIM];
__device__ __half g_hQ [SEQ * DIM];
__device__ __half g_hK [SEQ * DIM];
__device__ __half g_hVt[DIM * SEQ];            // V^T (K-major B for PV)
__device__ __half g_hP [(size_t)SEQ * SEQ];    // unscaled exp(s - m_b), half
__device__ float  g_Mb [(size_t)SEQ * 64];     // per (row, block) max
__device__ float  g_Lb [(size_t)SEQ * 64];     // per (row, block) sum
__device__ __half g_sc [(size_t)SEQ * 64];     // per (row, block) scale e^{mb-m}/L
__device__ float  g_part[2048 * DIM];          // PV split-K partials (rows 6144..8191)

// ---------------------------------------------------------------------------
__device__ __forceinline__ uint32_t smem_u32(const void* p) {
    uint32_t a;
    asm("{ .reg .u64 t; cvta.to.shared.u64 t, %1; cvt.u32.u64 %0, t; }" : "=r"(a) : "l"(p));
    return a;
}
__device__ __forceinline__ void mma_f16(float* c, const uint32_t* a, const uint32_t* b) {
    asm volatile(
        "mma.sync.aligned.m16n8k16.row.col.f32.f16.f16.f32 "
        "{%0,%1,%2,%3}, {%4,%5,%6,%7}, {%8,%9}, {%0,%1,%2,%3};\n"
        : "+f"(c[0]), "+f"(c[1]), "+f"(c[2]), "+f"(c[3])
        : "r"(a[0]), "r"(a[1]), "r"(a[2]), "r"(a[3]), "r"(b[0]), "r"(b[1]));
}
__device__ __forceinline__ void ldsm4(uint32_t* r, uint32_t addr) {
    asm volatile("ldmatrix.sync.aligned.m8n8.x4.shared.b16 {%0,%1,%2,%3}, [%4];"
                 : "=r"(r[0]), "=r"(r[1]), "=r"(r[2]), "=r"(r[3]) : "r"(addr));
}
__device__ __forceinline__ uint32_t hmul2_u(uint32_t a, __half2 s) {
    __half2 v = *(__half2*)&a;
    v = __hmul2(v, s);
    return *(uint32_t*)&v;
}
#define CP16(dst, src) \
    asm volatile("cp.async.cg.shared.global [%0], [%1], 16;" :: "r"(dst), "l"(src) : "memory")

#define STAGE_B (2 * 128 * 40 * 2)   // 20480 bytes per stage
#define BOFF    (128 * 40 * 2)

#define PRODUCE(t) do {                                                       \
        const __half* _Ab = Ag + (t) * 32;                                    \
        const __half* _Bb = Bg + (t) * 32;                                    \
        const uint32_t _sA = sbase + ((t) & 3) * STAGE_B;                     \
        const uint32_t _sB = _sA + BOFF;                                      \
        _Pragma("unroll")                                                     \
        for (int _j = 0; _j < 4; _j++) {                                      \
            int _q = _j * 128 + tid;                                          \
            int _r = _q >> 2, _c = _q & 3;                                    \
            uint32_t _so = _r * 80 + _c * 16;                                 \
            CP16(_sA + _so, _Ab + (size_t)_r * lda + _c * 8);                 \
            CP16(_sB + _so, _Bb + (size_t)_r * ldb + _c * 8);                 \
        }                                                                     \
        asm volatile("cp.async.commit_group;" ::: "memory");                  \
    } while (0)

#define MAINLOOP()                                                            \
    PRODUCE(0); PRODUCE(1); PRODUCE(2);                                       \
    for (int i = 0; i < NT; i++) {                                            \
        asm volatile("cp.async.wait_group 2;" ::: "memory");                  \
        __syncthreads();                                                      \
        if (i + 3 < NT) PRODUCE(i + 3);                                       \
        else asm volatile("cp.async.commit_group;" ::: "memory");             \
        const uint32_t stA = sbase + (i & 3) * STAGE_B;                       \
        const uint32_t stB = stA + BOFF;                                      \
        _Pragma("unroll")                                                     \
        for (int ks = 0; ks < 2; ks++) {                                      \
            const uint32_t kbyte = (uint32_t)(ks * 32);                       \
            uint32_t a[4][4], b[8][2];                                        \
            _Pragma("unroll")                                                 \
            for (int mi = 0; mi < 4; mi++)                                    \
                ldsm4(a[mi], stA + a_off + (uint32_t)(mi * 16 * 80) + kbyte); \
            _Pragma("unroll")                                                 \
            for (int np = 0; np < 4; np++) {                                  \
                uint32_t rb[4];                                               \
                ldsm4(rb, stB + b_off + (uint32_t)(np * 16 * 80) + kbyte);    \
                b[np*2][0] = rb[0]; b[np*2][1] = rb[1];                       \
                b[np*2+1][0] = rb[2]; b[np*2+1][1] = rb[3];                   \
            }                                                                 \
            _Pragma("unroll")                                                 \
            for (int mi = 0; mi < 4; mi++)                                    \
                _Pragma("unroll")                                             \
                for (int ni = 0; ni < 8; ni++)                                \
                    mma_f16(acc[mi][ni], a[mi], b[ni]);                       \
        }                                                                     \
    }

#define DECL_COMMON()                                                         \
    extern __shared__ __half smem[];                                          \
    const uint32_t sbase = smem_u32(smem);                                    \
    const int tid = threadIdx.x, wid = tid >> 5, lane = tid & 31;             \
    const int l4 = lane >> 2, lq = lane & 3;                                  \
    const int wm = (wid >> 1) * 64, wn = (wid & 1) * 64;                      \
    const int lt = lane >> 3, lr = lane & 7;                                  \
    const uint32_t a_off = (uint32_t)((wm + (lt & 1) * 8 + lr) * 80 + (lt >> 1) * 16); \
    const uint32_t b_off = (uint32_t)((wn + (lt >> 1) * 8 + lr) * 80 + (lt & 1) * 16); \
    float acc[4][8][4];                                                       \
    _Pragma("unroll")                                                         \
    for (int i = 0; i < 4; i++)                                               \
        _Pragma("unroll")                                                     \
        for (int j = 0; j < 8; j++)                                           \
            _Pragma("unroll")                                                 \
            for (int e = 0; e < 4; e++) acc[i][j][e] = 0.f;

// ---------------------------------------------------------------------------
// Fused QKV projection: grid (24, 64). bx/8 selects {Q, K, V}.
// ---------------------------------------------------------------------------
__global__ void __launch_bounds__(128, 2)
gemm_qkv(const __half* __restrict__ X,
         const __half* __restrict__ Wq, const __half* __restrict__ Wk,
         const __half* __restrict__ Wv,
         __half* __restrict__ Q, __half* __restrict__ Kh, __half* __restrict__ Vt)
{
    const int bxs = blockIdx.x;
    const int sel = bxs >> 3;
    const int bx  = bxs & 7;
    const int by  = blockIdx.y;
    const int lda = DIM, ldb = DIM;
    const int NT  = DIM >> 5;

    DECL_COMMON();
    const __half* Ag = X + (size_t)by * 128 * lda;
    const __half* W  = (sel == 0) ? Wq : (sel == 1) ? Wk : Wv;
    const __half* Bg = W + (size_t)bx * 128 * ldb;

    MAINLOOP();

    if (sel < 2) {
        __half* C = (sel == 0) ? Q : Kh;
#pragma unroll
        for (int mi = 0; mi < 4; mi++) {
            const int gr0 = by * 128 + wm + mi * 16 + l4;
            const int gr1 = gr0 + 8;
#pragma unroll
            for (int ni = 0; ni < 8; ni++) {
                const int gc = bx * 128 + wn + ni * 8 + 2 * lq;
                *(__half2*)(C + (size_t)gr0 * DIM + gc) = __floats2half2_rn(acc[mi][ni][0], acc[mi][ni][1]);
                *(__half2*)(C + (size_t)gr1 * DIM + gc) = __floats2half2_rn(acc[mi][ni][2], acc[mi][ni][3]);
            }
        }
    } else {
        __syncthreads();
        __half* sT = smem;                       // [128][136] halves
#pragma unroll
        for (int mi = 0; mi < 4; mi++) {
            const int r0 = wm + mi * 16 + l4;
            const int r1 = r0 + 8;
#pragma unroll
            for (int ni = 0; ni < 8; ni++) {
                const int c = wn + ni * 8 + 2 * lq;
                sT[(size_t)c * 136 + r0]       = __float2half_rn(acc[mi][ni][0]);
                sT[(size_t)(c + 1) * 136 + r0] = __float2half_rn(acc[mi][ni][1]);
                sT[(size_t)c * 136 + r1]       = __float2half_rn(acc[mi][ni][2]);
                sT[(size_t)(c + 1) * 136 + r1] = __float2half_rn(acc[mi][ni][3]);
            }
        }
        __syncthreads();
        const int d = tid;
        __half* dst = Vt + (size_t)(bx * 128 + d) * SEQ + (size_t)by * 128;
        const __half* src = sT + (size_t)d * 136;
#pragma unroll
        for (int j = 0; j < 16; j++)
            *(float4*)(dst + j * 8) = *(const float4*)(src + j * 8);
    }
}

// ---------------------------------------------------------------------------
// QK^T with fused block-softmax epilogue. TRIANGULAR grid: 2080 CTAs,
// bid -> (bx, by) with bx <= by (no dead CTAs).
// ---------------------------------------------------------------------------
__global__ void __launch_bounds__(128, 2)
gemm_qk(const __half* __restrict__ A, const __half* __restrict__ B,
        __half* __restrict__ P, float* __restrict__ Mb, float* __restrict__ Lb)
{
    const int bid = blockIdx.x;                  // 0..2079
    int by = (int)((sqrtf(8.f * bid + 1.f) - 1.f) * 0.5f);
    while ((by + 1) * (by + 2) / 2 <= bid) by++;
    while (by * (by + 1) / 2 > bid) by--;
    const int bx = bid - by * (by + 1) / 2;

    const int lda = DIM, ldb = DIM;
    const int NT = DIM >> 5;

    DECL_COMMON();
    const __half* Ag = A + (size_t)by * 128 * lda;
    const __half* Bg = B + (size_t)bx * 128 * ldb;

    MAINLOOP();

    __syncthreads();
    float* smax = (float*)smem;
    float* ssum = smax + 256;

    float m0[4], m1[4];
#pragma unroll
    for (int mi = 0; mi < 4; mi++) {
        const int r0 = wm + mi * 16 + l4;
        const int r1 = r0 + 8;
        float a0 = -3.4e38f, a1 = -3.4e38f;
#pragma unroll
        for (int ni = 0; ni < 8; ni++) {
            const int c = wn + ni * 8 + 2 * lq;
            float v0 = acc[mi][ni][0] * 0.03125f;
            float v1 = acc[mi][ni][1] * 0.03125f;
            float v2 = acc[mi][ni][2] * 0.03125f;
            float v3 = acc[mi][ni][3] * 0.03125f;
            if (bx == by) {
                if (c     > r0) v0 = -1e30f;
                if (c + 1 > r0) v1 = -1e30f;
                if (c     > r1) v2 = -1e30f;
                if (c + 1 > r1) v3 = -1e30f;
            }
            acc[mi][ni][0] = v0; acc[mi][ni][1] = v1;
            acc[mi][ni][2] = v2; acc[mi][ni][3] = v3;
            a0 = fmaxf(a0, fmaxf(v0, v1));
            a1 = fmaxf(a1, fmaxf(v2, v3));
        }
        m0[mi] = a0; m1[mi] = a1;
    }
#pragma unroll
    for (int mi = 0; mi < 4; mi++) {
        m0[mi] = fmaxf(m0[mi], __shfl_xor_sync(0xffffffffu, m0[mi], 1));
        m0[mi] = fmaxf(m0[mi], __shfl_xor_sync(0xffffffffu, m0[mi], 2));
        m1[mi] = fmaxf(m1[mi], __shfl_xor_sync(0xffffffffu, m1[mi], 1));
        m1[mi] = fmaxf(m1[mi], __shfl_xor_sync(0xffffffffu, m1[mi], 2));
    }
    if (lq == 0) {
#pragma unroll
        for (int mi = 0; mi < 4; mi++) {
            const int r = wm + mi * 16 + l4;
            smax[(wid & 1) * 128 + r]     = m0[mi];
            smax[(wid & 1) * 128 + r + 8] = m1[mi];
        }
    }
    __syncthreads();
    float cm0[4], cm1[4];
#pragma unroll
    for (int mi = 0; mi < 4; mi++) {
        const int r = wm + mi * 16 + l4;
        cm0[mi] = fmaxf(smax[r],     smax[128 + r]);
        cm1[mi] = fmaxf(smax[r + 8], smax[128 + r + 8]);
    }

    float s0[4], s1[4];
#pragma unroll
    for (int mi = 0; mi < 4; mi++) {
        const size_t gr0 = (size_t)(by * 128 + wm + mi * 16 + l4);
        const size_t gr1 = gr0 + 8;
        float t0 = 0.f, t1 = 0.f;
#pragma unroll
        for (int ni = 0; ni < 8; ni++) {
            const int gc = bx * 128 + wn + ni * 8 + 2 * lq;
            float e0 = __expf(acc[mi][ni][0] - cm0[mi]);
            float e1 = __expf(acc[mi][ni][1] - cm0[mi]);
            float e2 = __expf(acc[mi][ni][2] - cm1[mi]);
            float e3 = __expf(acc[mi][ni][3] - cm1[mi]);
            t0 += e0 + e1; t1 += e2 + e3;
            *(__half2*)(P + gr0 * SEQ + gc) = __floats2half2_rn(e0, e1);
            *(__half2*)(P + gr1 * SEQ + gc) = __floats2half2_rn(e2, e3);
        }
        s0[mi] = t0; s1[mi] = t1;
    }
#pragma unroll
    for (int mi = 0; mi < 4; mi++) {
        s0[mi] += __shfl_xor_sync(0xffffffffu, s0[mi], 1);
        s0[mi] += __shfl_xor_sync(0xffffffffu, s0[mi], 2);
        s1[mi] += __shfl_xor_sync(0xffffffffu, s1[mi], 1);
        s1[mi] += __shfl_xor_sync(0xffffffffu, s1[mi], 2);
    }
    if (lq == 0) {
#pragma unroll
        for (int mi = 0; mi < 4; mi++) {
            const int r = wm + mi * 16 + l4;
            ssum[(wid & 1) * 128 + r]     = s0[mi];
            ssum[(wid & 1) * 128 + r + 8] = s1[mi];
        }
    }
    __syncthreads();
    if ((wid & 1) == 0 && lq == 0) {
#pragma unroll
        for (int mi = 0; mi < 4; mi++) {
            const int r = wm + mi * 16 + l4;
            const size_t g0 = (size_t)(by * 128 + r) * 64 + bx;
            const size_t g1 = (size_t)(by * 128 + r + 8) * 64 + bx;
            Mb[g0] = cm0[mi]; Lb[g0] = ssum[r] + ssum[128 + r];
            Mb[g1] = cm1[mi]; Lb[g1] = ssum[r + 8] + ssum[128 + r + 8];
        }
    }
}

// ---------------------------------------------------------------------------
__global__ void __launch_bounds__(256)
stats_k(const float* __restrict__ Mb, const float* __restrict__ Lb,
        __half* __restrict__ SC)
{
    const int row  = blockIdx.x * 8 + (threadIdx.x >> 5);
    const int lane = threadIdx.x & 31;
    const int nb   = (row >> 7) + 1;
    const size_t base = (size_t)row * 64;

    float mA = (lane      < nb) ? Mb[base + lane]      : -3.4e38f;
    float mB = (lane + 32 < nb) ? Mb[base + lane + 32] : -3.4e38f;
    float mm = fmaxf(mA, mB);
#pragma unroll
    for (int s = 16; s > 0; s >>= 1)
        mm = fmaxf(mm, __shfl_xor_sync(0xffffffffu, mm, s));

    float eA = (lane      < nb) ? __expf(mA - mm) : 0.f;
    float eB = (lane + 32 < nb) ? __expf(mB - mm) : 0.f;
    float part = (lane < nb ? Lb[base + lane] * eA : 0.f)
               + (lane + 32 < nb ? Lb[base + lane + 32] * eB : 0.f);
#pragma unroll
    for (int s = 16; s > 0; s >>= 1)
        part += __shfl_xor_sync(0xffffffffu, part, s);
    const float inv = 1.f / part;

    if (lane < nb)      SC[base + lane]      = __float2half(eA * inv);
    if (lane + 32 < nb) SC[base + lane + 32] = __float2half(eB * inv);
}

// ---------------------------------------------------------------------------
// PV with split-K LPT schedule: grid (8, 80). blockIdx.y -> (by, b0, nu, dst):
//   r<16  : by=47-r,        full row (units 48..33)            -> out
//   r<32  : by=63-(r-16),   part0: K-blocks [0,32)             -> g_part
//   r<64  : pairs p=(r-32)/2: even -> by=31-p full (32..17)    -> out
//                             odd  -> by=63-p part1 [32,by+1)  -> out
//   r<80  : by=15-(r-64),   full row (units 16..1)             -> out
// Every out row-block has exactly one writer; rows >= 6144 get g_part added
// by pv_fixup afterwards. Descending-work order = LPT (longest first).
// ---------------------------------------------------------------------------
__global__ void __launch_bounds__(128, 2)
gemm_pv(const __half* __restrict__ Phat, const __half* __restrict__ Vt,
        const __half* __restrict__ SC, float* __restrict__ Out,
        float* __restrict__ Part)
{
    const int bx = blockIdx.x;
    const int r  = blockIdx.y;
    int by, b0, nu, dst;
    if (r < 16)      { by = 47 - r;        b0 = 0;  nu = by + 1;      dst = 0; }
    else if (r < 32) { by = 63 - (r - 16); b0 = 0;  nu = 32;          dst = 1; }
    else if (r < 64) { int p = (r - 32) >> 1;
                       if (((r - 32) & 1) == 0) { by = 31 - p; b0 = 0;  nu = by + 1;      dst = 0; }
                       else                     { by = 63 - p; b0 = 32; nu = by + 1 - 32; dst = 0; } }
    else             { by = 15 - (r - 64); b0 = 0;  nu = by + 1;      dst = 0; }

    const int lda = SEQ, ldb = SEQ;
    const int NT = nu * 4;

    DECL_COMMON();
    const __half* Ag = Phat + (size_t)by * 128 * lda + (size_t)b0 * 128;
    const __half* Bg = Vt + (size_t)bx * 128 * ldb + (size_t)b0 * 128;
    const size_t scbase = (size_t)(by * 128) * 64;

    __half2 scb[2][4][2];
#define LOADSC(b, buf) do {                                                   \
        _Pragma("unroll")                                                     \
        for (int _mi = 0; _mi < 4; _mi++) {                                   \
            const __half* _p = SC + scbase + (size_t)(wm + _mi * 16 + l4) * 64 + (b); \
            scb[buf][_mi][0] = __half2half2(_p[0]);                           \
            scb[buf][_mi][1] = __half2half2(_p[8 * 64]);                      \
        }                                                                     \
    } while (0)

    LOADSC(b0, 0);

    PRODUCE(0); PRODUCE(1); PRODUCE(2);
    for (int i = 0; i < NT; i++) {
        asm volatile("cp.async.wait_group 2;" ::: "memory");
        __syncthreads();
        if (i + 3 < NT) PRODUCE(i + 3);
        else asm volatile("cp.async.commit_group;" ::: "memory");

        if ((i & 3) == 1 && (i >> 2) + 1 < nu) LOADSC(b0 + (i >> 2) + 1, ((i >> 2) + 1) & 1);
        const int sbuf = (i >> 2) & 1;

        const uint32_t stA = sbase + (i & 3) * STAGE_B;
        const uint32_t stB = stA + BOFF;
#pragma unroll
        for (int ks = 0; ks < 2; ks++) {
            const uint32_t kbyte = (uint32_t)(ks * 32);
            uint32_t a[4][4], b[8][2];
#pragma unroll
            for (int mi = 0; mi < 4; mi++) {
                ldsm4(a[mi], stA + a_off + (uint32_t)(mi * 16 * 80) + kbyte);
                a[mi][0] = hmul2_u(a[mi][0], scb[sbuf][mi][0]);
                a[mi][2] = hmul2_u(a[mi][2], scb[sbuf][mi][0]);
                a[mi][1] = hmul2_u(a[mi][1], scb[sbuf][mi][1]);
                a[mi][3] = hmul2_u(a[mi][3], scb[sbuf][mi][1]);
            }
#pragma unroll
            for (int np = 0; np < 4; np++) {
                uint32_t rb[4];
                ldsm4(rb, stB + b_off + (uint32_t)(np * 16 * 80) + kbyte);
                b[np*2][0] = rb[0]; b[np*2][1] = rb[1];
                b[np*2+1][0] = rb[2]; b[np*2+1][1] = rb[3];
            }
#pragma unroll
            for (int mi = 0; mi < 4; mi++)
#pragma unroll
                for (int ni = 0; ni < 8; ni++)
                    mma_f16(acc[mi][ni], a[mi], b[ni]);
        }
    }
#undef LOADSC

    float* C = dst ? (Part - (size_t)6144 * DIM) : Out;   // Part indexed by (row-6144)
#pragma unroll
    for (int mi = 0; mi < 4; mi++) {
        const int gr0 = by * 128 + wm + mi * 16 + l4;
        const int gr1 = gr0 + 8;
#pragma unroll
        for (int ni = 0; ni < 8; ni++) {
            const int gc = bx * 128 + wn + ni * 8 + 2 * lq;
            *(float2*)(C + (size_t)gr0 * DIM + gc) = make_float2(acc[mi][ni][0], acc[mi][ni][1]);
            *(float2*)(C + (size_t)gr1 * DIM + gc) = make_float2(acc[mi][ni][2], acc[mi][ni][3]);
        }
    }
}

// add split-K partials into out rows [6144, 8192)
__global__ void __launch_bounds__(256)
pv_fixup(float* __restrict__ Out, const float* __restrict__ Part)
{
    const size_t i = ((size_t)blockIdx.x * 256 + threadIdx.x) * 4;
    float4 a = *(const float4*)(Out + (size_t)6144 * DIM + i);
    float4 b = *(const float4*)(Part + i);
    a.x += b.x; a.y += b.y; a.z += b.z; a.w += b.w;
    *(float4*)(Out + (size_t)6144 * DIM + i) = a;
}

// ---------------------------------------------------------------------------
__global__ void __launch_bounds__(256)
conv_all(const float* __restrict__ x,  const float* __restrict__ wq,
         const float* __restrict__ wk, const float* __restrict__ wv,
         __half* __restrict__ hX,  __half* __restrict__ hWq,
         __half* __restrict__ hWk, __half* __restrict__ hWv)
{
    const long long NX = (long long)SEQ * DIM / 4;
    const long long NW = (long long)DIM * DIM / 4;
    long long f4 = (long long)blockIdx.x * 256 + threadIdx.x;
    const float* s; __half* d; long long off;
    if      (f4 < NX)          { s = x;  d = hX;  off = f4; }
    else if (f4 < NX + NW)     { s = wq; d = hWq; off = f4 - NX; }
    else if (f4 < NX + 2 * NW) { s = wk; d = hWk; off = f4 - NX - NW; }
    else                       { s = wv; d = hWv; off = f4 - NX - 2 * NW; }
    float4 v = *(const float4*)(s + off * 4);
    *(__half2*)(d + off * 4)     = __floats2half2_rn(v.x, v.y);
    *(__half2*)(d + off * 4 + 2) = __floats2half2_rn(v.z, v.w);
}

// ---------------------------------------------------------------------------
extern "C" void kernel_launch(void* const* d_in, const int* in_sizes, int n_in,
                              void* d_out, int out_size)
{
    const float* x  = (const float*)d_in[0];
    const float* wq = (const float*)d_in[1];
    const float* wk = (const float*)d_in[2];
    const float* wv = (const float*)d_in[3];
    float* out = (float*)d_out;

    __half *hX, *hWq, *hWk, *hWv, *hQ, *hK, *hVt, *hP, *sc;
    float *Mb, *Lb, *part;
    cudaGetSymbolAddress((void**)&hX,   g_hX);
    cudaGetSymbolAddress((void**)&hWq,  g_hWq);
    cudaGetSymbolAddress((void**)&hWk,  g_hWk);
    cudaGetSymbolAddress((void**)&hWv,  g_hWv);
    cudaGetSymbolAddress((void**)&hQ,   g_hQ);
    cudaGetSymbolAddress((void**)&hK,   g_hK);
    cudaGetSymbolAddress((void**)&hVt,  g_hVt);
    cudaGetSymbolAddress((void**)&hP,   g_hP);
    cudaGetSymbolAddress((void**)&sc,   g_sc);
    cudaGetSymbolAddress((void**)&Mb,   g_Mb);
    cudaGetSymbolAddress((void**)&Lb,   g_Lb);
    cudaGetSymbolAddress((void**)&part, g_part);

    const int SMEM_DYN = 4 * STAGE_B;            // 81920 bytes
    cudaFuncSetAttribute(gemm_qkv, cudaFuncAttributeMaxDynamicSharedMemorySize, SMEM_DYN);
    cudaFuncSetAttribute(gemm_qk,  cudaFuncAttributeMaxDynamicSharedMemorySize, SMEM_DYN);
    cudaFuncSetAttribute(gemm_pv,  cudaFuncAttributeMaxDynamicSharedMemorySize, SMEM_DYN);

    const long long NCONV = (long long)SEQ * DIM / 4 + 3LL * DIM * DIM / 4;
    conv_all<<<(unsigned)((NCONV + 255) / 256), 256>>>(x, wq, wk, wv, hX, hWq, hWk, hWv);

    dim3 gthr(128);

    gemm_qkv<<<dim3(24, 64), gthr, SMEM_DYN>>>(hX, hWq, hWk, hWv, hQ, hK, hVt);

    gemm_qk<<<2080, gthr, SMEM_DYN>>>(hQ, hK, hP, Mb, Lb);

    stats_k<<<SEQ / 8, 256>>>(Mb, Lb, sc);

    gemm_pv<<<dim3(8, 80), gthr, SMEM_DYN>>>(hP, hVt, sc, out, part);

    pv_fixup<<<2048 * DIM / 1024, 256>>>(out, part);
}